// round 11
// baseline (speedup 1.0000x reference)
#include <cuda_runtime.h>
#include <cuda_bf16.h>
#include <cstdint>
#include <math.h>

// Problem constants
#define B_   2
#define S_   2048
#define H_   2048
#define NH_  16
#define HD_  128
#define M_   (B_ * S_)      // 4096
#define NQKV (3 * H_)       // 6144

// ---------------------------------------------------------------------------
// Scratch (device globals — allocation-free per harness rules)
// ---------------------------------------------------------------------------
__device__ __align__(256) float g_qkv[(size_t)M_ * NQKV];
__device__ __align__(256) float g_cos[S_ * 64];
__device__ __align__(256) float g_sin[S_ * 64];
// attention fragment arrays (hi/lo bf16 split)
__device__ __align__(256) uint32_t g_qf[(size_t)32 * 128 * 2048];
__device__ __align__(256) uint32_t g_kf[(size_t)32 * 32 * 8192];
__device__ __align__(256) uint32_t g_vf[(size_t)32 * 32 * 8192];
// GEMM fragment arrays
__device__ __align__(256) uint32_t g_xf[(size_t)M_ * H_];      // x A-frags
__device__ __align__(256) uint32_t g_cf[(size_t)M_ * H_];      // ctx A-frags
__device__ __align__(256) uint32_t g_wqkvf[(size_t)NQKV * H_]; // Wqkv B-frags
__device__ __align__(256) uint32_t g_wof[(size_t)H_ * H_];     // Wo B-frags

// ---------------------------------------------------------------------------
// Helpers
// ---------------------------------------------------------------------------
__device__ __forceinline__ void split2(float a, float b, uint32_t& hi, uint32_t& lo) {
    __nv_bfloat162 h = __floats2bfloat162_rn(a, b);
    float ra = a - __bfloat162float(h.x);
    float rb = b - __bfloat162float(h.y);
    __nv_bfloat162 l = __floats2bfloat162_rn(ra, rb);
    hi = *(uint32_t*)&h;
    lo = *(uint32_t*)&l;
}
#define MMA16816(cr, a, b0r, b1r)                                             \
    asm volatile("mma.sync.aligned.m16n8k16.row.col.f32.bf16.bf16.f32 "       \
        "{%0,%1,%2,%3}, {%4,%5,%6,%7}, {%8,%9}, {%0,%1,%2,%3};"               \
        : "+f"((cr)[0]), "+f"((cr)[1]), "+f"((cr)[2]), "+f"((cr)[3])          \
        : "r"((a).x), "r"((a).y), "r"((a).z), "r"((a).w), "r"(b0r), "r"(b1r))

__device__ __forceinline__ uint32_t smem_u32(const void* p) {
    uint32_t a;
    asm("{ .reg .u64 t; cvta.to.shared.u64 t, %1; cvt.u32.u64 %0, t; }" : "=r"(a) : "l"(p));
    return a;
}
#define CP_ASYNC16(dst, src) \
    asm volatile("cp.async.cg.shared.global [%0], [%1], 16;" :: "r"(dst), "l"(src))
#define CP_COMMIT() asm volatile("cp.async.commit_group;" ::: "memory")
#define CP_WAIT1()  asm volatile("cp.async.wait_group 1;" ::: "memory")
#define CP_WAIT0()  asm volatile("cp.async.wait_group 0;" ::: "memory")

// ---------------------------------------------------------------------------
// RoPE trig table (fp32 phase to match jax, accurate trig)
// ---------------------------------------------------------------------------
__global__ void trig_kernel() {
    int idx = blockIdx.x * blockDim.x + threadIdx.x;
    if (idx >= S_ * 64) return;
    int s = idx >> 6, i = idx & 63;
    float invf = (float)pow(10000.0, -(double)i / 64.0);
    float th = (float)s * invf;
    g_cos[idx] = (float)cos((double)th);
    g_sin[idx] = (float)sin((double)th);
}

// ---------------------------------------------------------------------------
// Activation -> A-fragment slabs (unchanged layout from R10, validated).
// AF[((mt*(K/16)+kt)*32 + lane)*8 + reg], reg 0-3 hi, 4-7 lo.
// ---------------------------------------------------------------------------
__global__ __launch_bounds__(256) void afrag_kernel(
    const float* __restrict__ A, uint32_t* __restrict__ AF, int M, int K)
{
    int idx = blockIdx.x * blockDim.x + threadIdx.x;
    int m = idx / (K >> 2), c4 = idx % (K >> 2);
    int k = 4 * c4;
    float4 v = *(const float4*)(A + (size_t)m * K + k);
    uint32_t h0, l0, h1, l1;
    split2(v.x, v.y, h0, l0);
    split2(v.z, v.w, h1, l1);
    int kt = k >> 4, kk = k & 15, tg = (kk & 7) >> 1, half_k = kk >> 3;
    int lane = (m & 7) * 4 + tg;
    int reg = ((m >> 3) & 1) + 2 * half_k;
    size_t base = (((size_t)(m >> 4) * (K >> 4) + kt) * 32 + lane) * 8 + reg;
    AF[base] = h0;     AF[base + 4] = l0;
    AF[base + 8] = h1; AF[base + 12] = l1;
}

// ---------------------------------------------------------------------------
// Weight W[K,N] -> B-fragment slabs (unchanged from R10, validated).
// BF[((nt*(K/16)+kt)*32 + lane)*4 + reg], reg 0-1 hi, 2-3 lo.
// ---------------------------------------------------------------------------
__global__ void wfrag_kernel(const float* __restrict__ W, uint32_t* __restrict__ BF,
                             int K, int N) {
    __shared__ float t[32][33];
    int k0 = blockIdx.x * 32, n0 = blockIdx.y * 32;
    int tx = threadIdx.x, ty = threadIdx.y;
    #pragma unroll
    for (int j = 0; j < 4; j++)
        t[ty + 8 * j][tx] = W[(size_t)(k0 + ty + 8 * j) * N + n0 + tx];
    __syncthreads();
    int id = ty * 32 + tx;
    #pragma unroll
    for (int u = 0; u < 2; u++) {
        int pid = id + 256 * u;
        int n_l = pid & 31, kp = pid >> 5;
        int k_l = 2 * kp;
        float va = t[k_l][n_l], vb = t[k_l + 1][n_l];
        uint32_t h, l; split2(va, vb, h, l);
        int n = n0 + n_l, k = k0 + k_l;
        int nt = n >> 3, gg = n & 7;
        int kt = k >> 4, kk = k & 15, reg = kk >> 3, tg = (kk & 7) >> 1;
        int lane = gg * 4 + tg;
        size_t w = (((size_t)nt * (K >> 4) + kt) * 32 + lane) * 4;
        BF[w + reg] = h;
        BF[w + 2 + reg] = l;
    }
}

// ---------------------------------------------------------------------------
// Fragment GEMM v2: CTA 256(M) x 128(N), 8 warps as 4(M) x 2(N) of 64x64
// warp tiles. K-step 32, 2-stage cp.async. 85B smem/MMA (was 128) -> tensor
// bound. 1 CTA/SM (高 regs), smem 96KB.
// ---------------------------------------------------------------------------
#define GEMM_SMEM 98304
__global__ __launch_bounds__(256, 1) void gemm_frag(
    const uint32_t* __restrict__ AF, const uint32_t* __restrict__ BF,
    float* __restrict__ C, int M, int N, int K)
{
    extern __shared__ uint32_t sh[];
    const uint32_t sb = smem_u32(sh);
    const int tid = threadIdx.x;
    const int wid = tid >> 5, lane = tid & 31;
    const int g = lane >> 2, tig = lane & 3;
    const int warp_m = wid >> 1, warp_n = wid & 1;
    const int mt0 = blockIdx.y * 16, nt0 = blockIdx.x * 16;
    const int KT = K >> 4;
    const int NIT = K >> 5;

    float c[4][8][4] = {};

    // stage: A 8192 words (16 mt x 2 kt x 32 x 8) + B 4096 words -> 48KB
    auto do_copy = [&](int st, int it) {
        const int kt0 = it * 2;
        uint32_t sbase = sb + st * 49152;
        #pragma unroll
        for (int u = 0; u < 8; u++) {                 // A: 2048 chunks
            int i = tid + 256 * u;
            int slab = i >> 6, within = i & 63;
            int mt_l = slab >> 1, kt_l = slab & 1;
            const uint32_t* src =
                AF + (((size_t)(mt0 + mt_l) * KT + kt0 + kt_l) * 256 + within * 4);
            CP_ASYNC16(sbase + (slab * 256 + within * 4) * 4, src);
        }
        #pragma unroll
        for (int u = 0; u < 4; u++) {                 // B: 1024 chunks
            int i = tid + 256 * u;
            int slab = i >> 5, within = i & 31;
            int nt_l = slab >> 1, kt_l = slab & 1;
            const uint32_t* src =
                BF + (((size_t)(nt0 + nt_l) * KT + kt0 + kt_l) * 128 + within * 4);
            CP_ASYNC16(sbase + 32768 + (slab * 128 + within * 4) * 4, src);
        }
    };

    do_copy(0, 0);
    CP_COMMIT();

    for (int it = 0; it < NIT; it++) {
        if (it + 1 < NIT) { do_copy((it + 1) & 1, it + 1); CP_COMMIT(); CP_WAIT1(); }
        else              { CP_WAIT0(); }
        __syncthreads();

        const uint32_t* s = sh + (it & 1) * 12288;
        #pragma unroll
        for (int tk = 0; tk < 2; tk++) {
            uint4 ahi[4], alo[4];
            #pragma unroll
            for (int i = 0; i < 4; i++) {
                int off = (((warp_m * 4 + i) * 2 + tk) * 32 + lane) * 8;
                ahi[i] = *(const uint4*)&s[off];
                alo[i] = *(const uint4*)&s[off + 4];
            }
            #pragma unroll
            for (int j = 0; j < 8; j++) {
                int off = 8192 + (((warp_n * 8 + j) * 2 + tk) * 32 + lane) * 4;
                uint4 bf = *(const uint4*)&s[off];
                #pragma unroll
                for (int i = 0; i < 4; i++) {
                    MMA16816(c[i][j], ahi[i], bf.x, bf.y);   // hh
                    MMA16816(c[i][j], ahi[i], bf.z, bf.w);   // hl
                    MMA16816(c[i][j], alo[i], bf.x, bf.y);   // lh
                }
            }
        }
        __syncthreads();
    }

    const int row0 = mt0 * 16, col0 = nt0 * 8;
    #pragma unroll
    for (int i = 0; i < 4; i++) {
        int r0 = row0 + (warp_m * 4 + i) * 16 + g;
        #pragma unroll
        for (int j = 0; j < 8; j++) {
            int cc = col0 + (warp_n * 8 + j) * 8 + tig * 2;
            *(float2*)(C + (size_t)r0 * N + cc)       = make_float2(c[i][j][0], c[i][j][1]);
            *(float2*)(C + (size_t)(r0 + 8) * N + cc) = make_float2(c[i][j][2], c[i][j][3]);
        }
    }
}

// ---------------------------------------------------------------------------
// Prep: qkv -> RoPE'd Q/K/V attention fragments (unchanged from R9/R10).
// ---------------------------------------------------------------------------
__global__ __launch_bounds__(256) void prep_kernel() {
    const int st = blockIdx.x, bh = blockIdx.y;
    const int b = bh >> 4, nh = bh & 15;
    const int s0 = st * 64;
    const int tid = threadIdx.x;
    __shared__ float vsm[64 * 132];

    #pragma unroll
    for (int u = 0; u < 8; u++) {
        int i = tid + 256 * u;
        int r = i >> 5, dg = i & 31;
        int s = s0 + r;
        size_t base = (size_t)(b * S_ + s) * NQKV + nh * HD_;
        float2 qx = *(const float2*)&g_qkv[base + 2 * dg];
        float2 qy = *(const float2*)&g_qkv[base + 2 * dg + 64];
        float2 kx = *(const float2*)&g_qkv[base + H_ + 2 * dg];
        float2 ky = *(const float2*)&g_qkv[base + H_ + 2 * dg + 64];
        float c0 = g_cos[s * 64 + 2 * dg], c1 = g_cos[s * 64 + 2 * dg + 1];
        float n0 = g_sin[s * 64 + 2 * dg], n1 = g_sin[s * 64 + 2 * dg + 1];

        float qa0 = qx.x * c0 - qy.x * n0, qa1 = qx.y * c1 - qy.y * n1;
        float qb0 = qy.x * c0 + qx.x * n0, qb1 = qy.y * c1 + qx.y * n1;
        float ka0 = kx.x * c0 - ky.x * n0, ka1 = kx.y * c1 - ky.y * n1;
        float kb0 = ky.x * c0 + kx.x * n0, kb1 = ky.y * c1 + kx.y * n1;

        int mq = s >> 4, rr = s & 15;
        size_t qb_ = (size_t)(bh * 128 + mq) * 2048;
        int tl = (s >> 3) & 7, gk = s & 7;
        size_t kb_ = (size_t)(bh * 32 + st) * 8192 + (size_t)tl * 1024;

        uint32_t h, l;
        {
            int p = dg, ks = p >> 3, pl = p & 7;
            int lane = (rr & 7) * 4 + (pl & 3);
            int reg = (rr >> 3) + 2 * (pl >> 2);
            split2(qa0, qa1, h, l);
            size_t w = qb_ + (size_t)ks * 256 + lane * 8;
            g_qf[w + reg] = h; g_qf[w + 4 + reg] = l;
            int klane = gk * 4 + (pl & 3), kreg = pl >> 2;
            split2(ka0, ka1, h, l);
            size_t wk = kb_ + (size_t)ks * 128 + klane * 4;
            g_kf[wk + kreg] = h; g_kf[wk + 2 + kreg] = l;
        }
        {
            int p = dg + 32, ks = p >> 3, pl = p & 7;
            int lane = (rr & 7) * 4 + (pl & 3);
            int reg = (rr >> 3) + 2 * (pl >> 2);
            split2(qb0, qb1, h, l);
            size_t w = qb_ + (size_t)ks * 256 + lane * 8;
            g_qf[w + reg] = h; g_qf[w + 4 + reg] = l;
            int klane = gk * 4 + (pl & 3), kreg = pl >> 2;
            split2(kb0, kb1, h, l);
            size_t wk = kb_ + (size_t)ks * 128 + klane * 4;
            g_kf[wk + kreg] = h; g_kf[wk + 2 + kreg] = l;
        }
    }

    #pragma unroll
    for (int u = 0; u < 8; u++) {
        int i = tid + 256 * u;
        int r = i >> 5, c4 = i & 31;
        size_t base = (size_t)(b * S_ + s0 + r) * NQKV + nh * HD_ + 2 * H_;
        float4 v = *(const float4*)&g_qkv[base + 4 * c4];
        float* d = &vsm[r * 132 + 4 * c4];
        d[0] = v.x; d[1] = v.y; d[2] = v.z; d[3] = v.w;
    }
    __syncthreads();

    {
        int kp = tid >> 3, nb = tid & 7;
        int ks2 = kp >> 3, tg2 = kp & 3, half = (kp >> 2) & 1;
        size_t vb_ = (size_t)(bh * 32 + st) * 8192;
        #pragma unroll
        for (int j = 0; j < 16; j++) {
            int n = nb + 8 * j;
            float va = vsm[2 * kp * 132 + n];
            float vv = vsm[(2 * kp + 1) * 132 + n];
            uint32_t h, l; split2(va, vv, h, l);
            int lane = nb * 4 + tg2;
            size_t w = vb_ + ((size_t)(j * 4 + ks2) * 32 + lane) * 4;
            g_vf[w + half] = h;
            g_vf[w + 2 + half] = l;
        }
    }
}

// ---------------------------------------------------------------------------
// MMA flash attention (unchanged from R10 — validated).
// ---------------------------------------------------------------------------
#define ATTN_SMEM 131072
__global__ __launch_bounds__(256, 1) void attn_mma() {
    extern __shared__ uint32_t asm_[];

    const int bh = blockIdx.y;
    const int qt = (int)(gridDim.x - 1 - blockIdx.x);
    const int q0 = qt * 128;
    const int tid = threadIdx.x, wid = tid >> 5, lane = tid & 31;
    const int g = lane >> 2, tig = lane & 3;
    const uint32_t sb = smem_u32(asm_);

    uint4 qhi[8], qlo[8];
    {
        const uint32_t* qf = g_qf + (size_t)(bh * 128 + (q0 >> 4) + wid) * 2048;
        #pragma unroll
        for (int ks = 0; ks < 8; ks++) {
            const uint32_t* p = qf + (ks * 32 + lane) * 8;
            qhi[ks] = *(const uint4*)p;
            qlo[ks] = *(const uint4*)(p + 4);
        }
    }

    float o[16][4];
    #pragma unroll
    for (int t = 0; t < 16; t++) { o[t][0] = o[t][1] = o[t][2] = o[t][3] = 0.f; }
    float ma = -1e30f, mb = -1e30f, la = 0.f, lb = 0.f;
    const int row_a = q0 + wid * 16 + g;
    const int row_b = row_a + 8;
    const float scale = 0.08838834764831845f;

    const int nkt = (q0 + 128) >> 6;

    auto do_copy = [&](int st, int kt) {
        const uint4* gk = (const uint4*)(g_kf + (size_t)(bh * 32 + kt) * 8192);
        const uint4* gv = (const uint4*)(g_vf + (size_t)(bh * 32 + kt) * 8192);
        uint32_t base = sb + st * 65536;
        #pragma unroll
        for (int u = 0; u < 8; u++) {
            int i = tid + 256 * u;
            CP_ASYNC16(base + i * 16, gk + i);
            CP_ASYNC16(base + 32768 + i * 16, gv + i);
        }
    };

    do_copy(0, 0);
    CP_COMMIT();

    for (int kt = 0; kt < nkt; kt++) {
        if (kt + 1 < nkt) { do_copy((kt + 1) & 1, kt + 1); CP_COMMIT(); CP_WAIT1(); }
        else              { CP_WAIT0(); }
        __syncthreads();
        const uint32_t* ksm = asm_ + (kt & 1) * 16384;
        const uint32_t* vsm = ksm + 8192;

        float c[8][4];
        #pragma unroll
        for (int t = 0; t < 8; t++) { c[t][0] = c[t][1] = c[t][2] = c[t][3] = 0.f; }
        #pragma unroll
        for (int ks = 0; ks < 8; ks++) {
            #pragma unroll
            for (int t = 0; t < 8; t++) {
                uint4 kf = *(const uint4*)&ksm[((t * 8 + ks) * 32 + lane) * 4];
                MMA16816(c[t], qhi[ks], kf.x, kf.y);
                MMA16816(c[t], qhi[ks], kf.z, kf.w);
                MMA16816(c[t], qlo[ks], kf.x, kf.y);
            }
        }

        float mxa = -1e30f, mxb = -1e30f;
        const bool need_mask = (kt * 64 + 63 > q0 + wid * 16);
        #pragma unroll
        for (int t = 0; t < 8; t++) {
            int k0 = kt * 64 + t * 8 + 2 * tig;
            float s0 = c[t][0] * scale, s1 = c[t][1] * scale;
            float s2 = c[t][2] * scale, s3 = c[t][3] * scale;
            if (need_mask) {
                if (k0 > row_a)     s0 = -1e30f;
                if (k0 + 1 > row_a) s1 = -1e30f;
                if (k0 > row_b)     s2 = -1e30f;
                if (k0 + 1 > row_b) s3 = -1e30f;
            }
            c[t][0] = s0; c[t][1] = s1; c[t][2] = s2; c[t][3] = s3;
            mxa = fmaxf(mxa, fmaxf(s0, s1));
            mxb = fmaxf(mxb, fmaxf(s2, s3));
        }
        mxa = fmaxf(mxa, __shfl_xor_sync(0xffffffffu, mxa, 1));
        mxa = fmaxf(mxa, __shfl_xor_sync(0xffffffffu, mxa, 2));
        mxb = fmaxf(mxb, __shfl_xor_sync(0xffffffffu, mxb, 1));
        mxb = fmaxf(mxb, __shfl_xor_sync(0xffffffffu, mxb, 2));

        float mna = fmaxf(ma, mxa), mnb = fmaxf(mb, mxb);
        float cra = __expf(ma - mna), crb = __expf(mb - mnb);
        ma = mna; mb = mnb; la *= cra; lb *= crb;
        #pragma unroll
        for (int t = 0; t < 16; t++) {
            o[t][0] *= cra; o[t][1] *= cra;
            o[t][2] *= crb; o[t][3] *= crb;
        }

        uint4 ahi[4], alo[4];
        #pragma unroll
        for (int k2 = 0; k2 < 4; k2++) {
            int t0 = 2 * k2, t1 = 2 * k2 + 1;
            float p0 = __expf(c[t0][0] - ma), p1 = __expf(c[t0][1] - ma);
            float p2 = __expf(c[t0][2] - mb), p3 = __expf(c[t0][3] - mb);
            float p4 = __expf(c[t1][0] - ma), p5 = __expf(c[t1][1] - ma);
            float p6 = __expf(c[t1][2] - mb), p7 = __expf(c[t1][3] - mb);
            la += p0 + p1 + p4 + p5;
            lb += p2 + p3 + p6 + p7;
            split2(p0, p1, ahi[k2].x, alo[k2].x);
            split2(p2, p3, ahi[k2].y, alo[k2].y);
            split2(p4, p5, ahi[k2].z, alo[k2].z);
            split2(p6, p7, ahi[k2].w, alo[k2].w);
        }

        #pragma unroll
        for (int k2 = 0; k2 < 4; k2++) {
            #pragma unroll
            for (int t2 = 0; t2 < 16; t2++) {
                uint4 vf = *(const uint4*)&vsm[((t2 * 4 + k2) * 32 + lane) * 4];
                MMA16816(o[t2], ahi[k2], vf.x, vf.y);
                MMA16816(o[t2], ahi[k2], vf.z, vf.w);
                MMA16816(o[t2], alo[k2], vf.x, vf.y);
            }
        }
        __syncthreads();
    }

    la += __shfl_xor_sync(0xffffffffu, la, 1);
    la += __shfl_xor_sync(0xffffffffu, la, 2);
    lb += __shfl_xor_sync(0xffffffffu, lb, 1);
    lb += __shfl_xor_sync(0xffffffffu, lb, 2);
    float ia = 1.f / la, ib = 1.f / lb;

    const int b = bh >> 4, nh = bh & 15;
    const int mt = b * 128 + ((q0 >> 4) + wid);
    #pragma unroll
    for (int t2 = 0; t2 < 16; t2++) {
        int kt2 = nh * 8 + (t2 >> 1);
        size_t base = (((size_t)mt * 128 + kt2) * 32 + lane) * 8 + 2 * (t2 & 1);
        uint32_t h, l;
        split2(o[t2][0] * ia, o[t2][1] * ia, h, l);
        g_cf[base] = h;     g_cf[base + 4] = l;
        split2(o[t2][2] * ib, o[t2][3] * ib, h, l);
        g_cf[base + 1] = h; g_cf[base + 5] = l;
    }
}

// ---------------------------------------------------------------------------
// kernel_launch
// ---------------------------------------------------------------------------
extern "C" void kernel_launch(void* const* d_in, const int* in_sizes, int n_in,
                              void* d_out, int out_size)
{
    const float* x    = (const float*)d_in[0];
    const float* wqkv = (const float*)d_in[2];
    const float* wo   = (const float*)d_in[3];

    float* qkv_p;
    uint32_t *xf_p, *cf_p, *wqkvf_p, *wof_p;
    cudaGetSymbolAddress((void**)&qkv_p, g_qkv);
    cudaGetSymbolAddress((void**)&xf_p, g_xf);
    cudaGetSymbolAddress((void**)&cf_p, g_cf);
    cudaGetSymbolAddress((void**)&wqkvf_p, g_wqkvf);
    cudaGetSymbolAddress((void**)&wof_p, g_wof);

    cudaFuncSetAttribute(gemm_frag, cudaFuncAttributeMaxDynamicSharedMemorySize, GEMM_SMEM);
    cudaFuncSetAttribute(attn_mma, cudaFuncAttributeMaxDynamicSharedMemorySize, ATTN_SMEM);

    trig_kernel<<<(S_ * 64 + 255) / 256, 256>>>();
    wfrag_kernel<<<dim3(H_ / 32, NQKV / 32), dim3(32, 8)>>>(wqkv, wqkvf_p, H_, NQKV);
    wfrag_kernel<<<dim3(H_ / 32, H_ / 32), dim3(32, 8)>>>(wo, wof_p, H_, H_);
    afrag_kernel<<<(M_ * H_ / 4) / 256, 256>>>(x, xf_p, M_, H_);

    gemm_frag<<<dim3(NQKV / 128, M_ / 256), 256, GEMM_SMEM>>>(xf_p, wqkvf_p, qkv_p, M_, NQKV, H_);
    prep_kernel<<<dim3(32, 32), 256>>>();
    attn_mma<<<dim3(S_ / 128, B_ * NH_), 256, ATTN_SMEM>>>();
    gemm_frag<<<dim3(H_ / 128, M_ / 256), 256, GEMM_SMEM>>>(cf_p, wof_p, (float*)d_out, M_, H_, H_);
}

// round 12
// speedup vs baseline: 1.5205x; 1.5205x over previous
#include <cuda_runtime.h>
#include <cuda_fp16.h>
#include <cstdint>
#include <math.h>

// Problem constants
#define B_   2
#define S_   2048
#define H_   2048
#define NH_  16
#define HD_  128
#define M_   (B_ * S_)      // 4096
#define NQKV (3 * H_)       // 6144

// ---------------------------------------------------------------------------
// Scratch (device globals — allocation-free per harness rules)
// ---------------------------------------------------------------------------
__device__ __align__(256) float g_qkv[(size_t)M_ * NQKV];
__device__ __align__(256) float g_cos[S_ * 64];
__device__ __align__(256) float g_sin[S_ * 64];
// attention fragment arrays: Q 2-term fp16 (8w), K/V single fp16 (2w)
__device__ __align__(256) uint32_t g_qf[(size_t)32 * 128 * 2048];
__device__ __align__(256) uint32_t g_kf[(size_t)32 * 32 * 4096];
__device__ __align__(256) uint32_t g_vf[(size_t)32 * 32 * 4096];
// GEMM fragment arrays: A 2-term fp16 (8w/lane/tile), B single fp16 (2w)
__device__ __align__(256) uint32_t g_xf[(size_t)M_ * H_];          // x A-frags
__device__ __align__(256) uint32_t g_cf[(size_t)M_ * H_];          // ctx A-frags
__device__ __align__(256) uint32_t g_wqkvf[(size_t)NQKV * H_ / 2]; // Wqkv B-frags
__device__ __align__(256) uint32_t g_wof[(size_t)H_ * H_ / 2];     // Wo B-frags

// ---------------------------------------------------------------------------
// Helpers: fp16 2-way split and single rounding
// ---------------------------------------------------------------------------
__device__ __forceinline__ void split2h(float a, float b, uint32_t& hi, uint32_t& lo) {
    __half2 h = __floats2half2_rn(a, b);
    float ra = a - __low2float(h);
    float rb = b - __high2float(h);
    __half2 l = __floats2half2_rn(ra, rb);
    hi = *(uint32_t*)&h;
    lo = *(uint32_t*)&l;
}
__device__ __forceinline__ uint32_t pack2h(float a, float b) {
    __half2 h = __floats2half2_rn(a, b);
    return *(uint32_t*)&h;
}
#define MMA16816(cr, a, b0r, b1r)                                             \
    asm volatile("mma.sync.aligned.m16n8k16.row.col.f32.f16.f16.f32 "         \
        "{%0,%1,%2,%3}, {%4,%5,%6,%7}, {%8,%9}, {%0,%1,%2,%3};"               \
        : "+f"((cr)[0]), "+f"((cr)[1]), "+f"((cr)[2]), "+f"((cr)[3])          \
        : "r"((a).x), "r"((a).y), "r"((a).z), "r"((a).w), "r"(b0r), "r"(b1r))

__device__ __forceinline__ uint32_t smem_u32(const void* p) {
    uint32_t a;
    asm("{ .reg .u64 t; cvta.to.shared.u64 t, %1; cvt.u32.u64 %0, t; }" : "=r"(a) : "l"(p));
    return a;
}
#define CP_ASYNC16(dst, src) \
    asm volatile("cp.async.cg.shared.global [%0], [%1], 16;" :: "r"(dst), "l"(src))
#define CP_COMMIT() asm volatile("cp.async.commit_group;" ::: "memory")
#define CP_WAIT1()  asm volatile("cp.async.wait_group 1;" ::: "memory")
#define CP_WAIT0()  asm volatile("cp.async.wait_group 0;" ::: "memory")

// ---------------------------------------------------------------------------
// RoPE trig table (fp32 phase to match jax, accurate trig)
// ---------------------------------------------------------------------------
__global__ void trig_kernel() {
    int idx = blockIdx.x * blockDim.x + threadIdx.x;
    if (idx >= S_ * 64) return;
    int s = idx >> 6, i = idx & 63;
    float invf = (float)pow(10000.0, -(double)i / 64.0);
    float th = (float)s * invf;
    g_cos[idx] = (float)cos((double)th);
    g_sin[idx] = (float)sin((double)th);
}

// ---------------------------------------------------------------------------
// Activation -> A-fragment slabs (layout as R10, fp16 2-term).
// AF[((mt*(K/16)+kt)*32 + lane)*8 + reg], reg 0-3 hi, 4-7 lo.
// ---------------------------------------------------------------------------
__global__ __launch_bounds__(256) void afrag_kernel(
    const float* __restrict__ A, uint32_t* __restrict__ AF, int M, int K)
{
    int idx = blockIdx.x * blockDim.x + threadIdx.x;
    int m = idx / (K >> 2), c4 = idx % (K >> 2);
    int k = 4 * c4;
    float4 v = *(const float4*)(A + (size_t)m * K + k);
    uint32_t h0, l0, h1, l1;
    split2h(v.x, v.y, h0, l0);
    split2h(v.z, v.w, h1, l1);
    int kt = k >> 4, kk = k & 15, tg = (kk & 7) >> 1, half_k = kk >> 3;
    int lane = (m & 7) * 4 + tg;
    int reg = ((m >> 3) & 1) + 2 * half_k;
    size_t base = (((size_t)(m >> 4) * (K >> 4) + kt) * 32 + lane) * 8 + reg;
    AF[base] = h0;     AF[base + 4] = l0;
    AF[base + 8] = h1; AF[base + 12] = l1;
}

// ---------------------------------------------------------------------------
// Weight W[K,N] -> B-fragment slabs, single fp16 term.
// BF[((nt*(K/16)+kt)*32 + lane)*2 + reg], reg = (k&15)>>3.
// ---------------------------------------------------------------------------
__global__ void wfrag_kernel(const float* __restrict__ W, uint32_t* __restrict__ BF,
                             int K, int N) {
    __shared__ float t[32][33];
    int k0 = blockIdx.x * 32, n0 = blockIdx.y * 32;
    int tx = threadIdx.x, ty = threadIdx.y;
    #pragma unroll
    for (int j = 0; j < 4; j++)
        t[ty + 8 * j][tx] = W[(size_t)(k0 + ty + 8 * j) * N + n0 + tx];
    __syncthreads();
    int id = ty * 32 + tx;
    #pragma unroll
    for (int u = 0; u < 2; u++) {
        int pid = id + 256 * u;
        int n_l = pid & 31, kp = pid >> 5;
        int k_l = 2 * kp;
        uint32_t h = pack2h(t[k_l][n_l], t[k_l + 1][n_l]);
        int n = n0 + n_l, k = k0 + k_l;
        int nt = n >> 3, gg = n & 7;
        int kt = k >> 4, kk = k & 15, reg = kk >> 3, tg = (kk & 7) >> 1;
        int lane = gg * 4 + tg;
        size_t w = (((size_t)nt * (K >> 4) + kt) * 32 + lane) * 2;
        BF[w + reg] = h;
    }
}

// ---------------------------------------------------------------------------
// Fragment GEMM (R10 shape: CTA 128x128, 8 warps 4x2, warp 32x64, 2 CTAs/SM).
// fp16: 2 MMAs per tile (A-hi, A-lo vs B). Stage: A 16KB + B 8KB = 24KB.
// ---------------------------------------------------------------------------
#define GEMM_SMEM 49152
__global__ __launch_bounds__(256, 2) void gemm_frag(
    const uint32_t* __restrict__ AF, const uint32_t* __restrict__ BF,
    float* __restrict__ C, int M, int N, int K)
{
    extern __shared__ uint32_t sh[];
    const uint32_t sb = smem_u32(sh);
    const int tid = threadIdx.x;
    const int wid = tid >> 5, lane = tid & 31;
    const int g = lane >> 2, tig = lane & 3;
    const int warp_m = wid >> 1, warp_n = wid & 1;
    const int mt0 = blockIdx.y * 8, nt0 = blockIdx.x * 16;
    const int KT = K >> 4;
    const int NIT = K >> 5;

    float c[2][8][4] = {};

    // stage: A 16 slabs x 256 words (1024 chunks) + B 32 slabs x 64 words (512 chunks)
    auto do_copy = [&](int st, int it) {
        const int kt0 = it * 2;
        uint32_t sbase = sb + st * 24576;
        #pragma unroll
        for (int u = 0; u < 4; u++) {
            int i = tid + 256 * u;                    // 0..1023
            int slab = i >> 6, within = i & 63;
            int mt_l = slab >> 1, kt_l = slab & 1;
            const uint32_t* src =
                AF + (((size_t)(mt0 + mt_l) * KT + kt0 + kt_l) * 256 + within * 4);
            CP_ASYNC16(sbase + (slab * 256 + within * 4) * 4, src);
        }
        #pragma unroll
        for (int u = 0; u < 2; u++) {
            int i = tid + 256 * u;                    // 0..511
            int slab = i >> 4, within = i & 15;
            int nt_l = slab >> 1, kt_l = slab & 1;
            const uint32_t* src =
                BF + (((size_t)(nt0 + nt_l) * KT + kt0 + kt_l) * 64 + within * 4);
            CP_ASYNC16(sbase + 16384 + (slab * 64 + within * 4) * 4, src);
        }
    };

    do_copy(0, 0);
    CP_COMMIT();

    for (int it = 0; it < NIT; it++) {
        if (it + 1 < NIT) { do_copy((it + 1) & 1, it + 1); CP_COMMIT(); CP_WAIT1(); }
        else              { CP_WAIT0(); }
        __syncthreads();

        const uint32_t* s = sh + (it & 1) * 6144;
        #pragma unroll
        for (int tk = 0; tk < 2; tk++) {
            uint4 ahi[2], alo[2];
            #pragma unroll
            for (int i = 0; i < 2; i++) {
                int off = (((warp_m * 2 + i) * 2 + tk) * 32 + lane) * 8;
                ahi[i] = *(const uint4*)&s[off];
                alo[i] = *(const uint4*)&s[off + 4];
            }
            #pragma unroll
            for (int j = 0; j < 8; j++) {
                int off = 4096 + (((warp_n * 8 + j) * 2 + tk) * 32 + lane) * 2;
                uint2 bf = *(const uint2*)&s[off];
                #pragma unroll
                for (int i = 0; i < 2; i++) {
                    MMA16816(c[i][j], ahi[i], bf.x, bf.y);   // hi x B
                    MMA16816(c[i][j], alo[i], bf.x, bf.y);   // lo x B
                }
            }
        }
        __syncthreads();
    }

    const int row0 = mt0 * 16, col0 = nt0 * 8;
    #pragma unroll
    for (int i = 0; i < 2; i++) {
        int r0 = row0 + (warp_m * 2 + i) * 16 + g;
        #pragma unroll
        for (int j = 0; j < 8; j++) {
            int cc = col0 + (warp_n * 8 + j) * 8 + tig * 2;
            *(float2*)(C + (size_t)r0 * N + cc)       = make_float2(c[i][j][0], c[i][j][1]);
            *(float2*)(C + (size_t)(r0 + 8) * N + cc) = make_float2(c[i][j][2], c[i][j][3]);
        }
    }
}

// ---------------------------------------------------------------------------
// Prep: qkv -> RoPE'd Q (2-term) / K,V (1-term) fp16 fragments.
// g_kf slab per (bh,kt): [tl 0..7][ks 0..7][lane]x2 words (4096 words)
// g_vf slab per (bh,kt): [t' 0..15][ks' 0..3][lane]x2 words (4096 words)
// ---------------------------------------------------------------------------
__global__ __launch_bounds__(256) void prep_kernel() {
    const int st = blockIdx.x, bh = blockIdx.y;
    const int b = bh >> 4, nh = bh & 15;
    const int s0 = st * 64;
    const int tid = threadIdx.x;
    __shared__ float vsm[64 * 132];

    #pragma unroll
    for (int u = 0; u < 8; u++) {
        int i = tid + 256 * u;
        int r = i >> 5, dg = i & 31;
        int s = s0 + r;
        size_t base = (size_t)(b * S_ + s) * NQKV + nh * HD_;
        float2 qx = *(const float2*)&g_qkv[base + 2 * dg];
        float2 qy = *(const float2*)&g_qkv[base + 2 * dg + 64];
        float2 kx = *(const float2*)&g_qkv[base + H_ + 2 * dg];
        float2 ky = *(const float2*)&g_qkv[base + H_ + 2 * dg + 64];
        float c0 = g_cos[s * 64 + 2 * dg], c1 = g_cos[s * 64 + 2 * dg + 1];
        float n0 = g_sin[s * 64 + 2 * dg], n1 = g_sin[s * 64 + 2 * dg + 1];

        float qa0 = qx.x * c0 - qy.x * n0, qa1 = qx.y * c1 - qy.y * n1;
        float qb0 = qy.x * c0 + qx.x * n0, qb1 = qy.y * c1 + qx.y * n1;
        float ka0 = kx.x * c0 - ky.x * n0, ka1 = kx.y * c1 - ky.y * n1;
        float kb0 = ky.x * c0 + kx.x * n0, kb1 = ky.y * c1 + kx.y * n1;

        int mq = s >> 4, rr = s & 15;
        size_t qb_ = (size_t)(bh * 128 + mq) * 2048;
        int tl = (s >> 3) & 7, gk = s & 7;
        size_t kb_ = (size_t)(bh * 32 + st) * 4096 + (size_t)tl * 512;

        uint32_t h, l;
        {
            int p = dg, ks = p >> 3, pl = p & 7;
            int lane = (rr & 7) * 4 + (pl & 3);
            int reg = (rr >> 3) + 2 * (pl >> 2);
            split2h(qa0, qa1, h, l);
            size_t w = qb_ + (size_t)ks * 256 + lane * 8;
            g_qf[w + reg] = h; g_qf[w + 4 + reg] = l;
            int klane = gk * 4 + (pl & 3), kreg = pl >> 2;
            g_kf[kb_ + (size_t)ks * 64 + klane * 2 + kreg] = pack2h(ka0, ka1);
        }
        {
            int p = dg + 32, ks = p >> 3, pl = p & 7;
            int lane = (rr & 7) * 4 + (pl & 3);
            int reg = (rr >> 3) + 2 * (pl >> 2);
            split2h(qb0, qb1, h, l);
            size_t w = qb_ + (size_t)ks * 256 + lane * 8;
            g_qf[w + reg] = h; g_qf[w + 4 + reg] = l;
            int klane = gk * 4 + (pl & 3), kreg = pl >> 2;
            g_kf[kb_ + (size_t)ks * 64 + klane * 2 + kreg] = pack2h(kb0, kb1);
        }
    }

    #pragma unroll
    for (int u = 0; u < 8; u++) {
        int i = tid + 256 * u;
        int r = i >> 5, c4 = i & 31;
        size_t base = (size_t)(b * S_ + s0 + r) * NQKV + nh * HD_ + 2 * H_;
        float4 v = *(const float4*)&g_qkv[base + 4 * c4];
        float* d = &vsm[r * 132 + 4 * c4];
        d[0] = v.x; d[1] = v.y; d[2] = v.z; d[3] = v.w;
    }
    __syncthreads();

    {
        int kp = tid >> 3, nb = tid & 7;
        int ks2 = kp >> 3, tg2 = kp & 3, half = (kp >> 2) & 1;
        size_t vb_ = (size_t)(bh * 32 + st) * 4096;
        #pragma unroll
        for (int j = 0; j < 16; j++) {
            int n = nb + 8 * j;
            uint32_t h = pack2h(vsm[2 * kp * 132 + n], vsm[(2 * kp + 1) * 132 + n]);
            int lane = nb * 4 + tg2;
            g_vf[vb_ + ((size_t)(j * 4 + ks2) * 32 + lane) * 2 + half] = h;
        }
    }
}

// ---------------------------------------------------------------------------
// MMA flash attention, fp16 (Q/P 2-term, K/V 1-term -> 2 MMAs per tile).
// cp.async double-buffered; epilogue writes GEMM2 A-frags (g_cf) directly.
// ---------------------------------------------------------------------------
#define ATTN_SMEM 65536
__global__ __launch_bounds__(256, 1) void attn_mma() {
    extern __shared__ uint32_t asm_[];   // stage: K 4096 + V 4096 words (32KB)

    const int bh = blockIdx.y;
    const int qt = (int)(gridDim.x - 1 - blockIdx.x);
    const int q0 = qt * 128;
    const int tid = threadIdx.x, wid = tid >> 5, lane = tid & 31;
    const int g = lane >> 2, tig = lane & 3;
    const uint32_t sb = smem_u32(asm_);

    uint4 qhi[8], qlo[8];
    {
        const uint32_t* qf = g_qf + (size_t)(bh * 128 + (q0 >> 4) + wid) * 2048;
        #pragma unroll
        for (int ks = 0; ks < 8; ks++) {
            const uint32_t* p = qf + (ks * 32 + lane) * 8;
            qhi[ks] = *(const uint4*)p;
            qlo[ks] = *(const uint4*)(p + 4);
        }
    }

    float o[16][4];
    #pragma unroll
    for (int t = 0; t < 16; t++) { o[t][0] = o[t][1] = o[t][2] = o[t][3] = 0.f; }
    float ma = -1e30f, mb = -1e30f, la = 0.f, lb = 0.f;
    const int row_a = q0 + wid * 16 + g;
    const int row_b = row_a + 8;
    const float scale = 0.08838834764831845f;

    const int nkt = (q0 + 128) >> 6;

    auto do_copy = [&](int st, int kt) {
        const uint4* gk = (const uint4*)(g_kf + (size_t)(bh * 32 + kt) * 4096);
        const uint4* gv = (const uint4*)(g_vf + (size_t)(bh * 32 + kt) * 4096);
        uint32_t base = sb + st * 32768;
        #pragma unroll
        for (int u = 0; u < 4; u++) {
            int i = tid + 256 * u;                 // 0..1023
            CP_ASYNC16(base + i * 16, gk + i);
            CP_ASYNC16(base + 16384 + i * 16, gv + i);
        }
    };

    do_copy(0, 0);
    CP_COMMIT();

    for (int kt = 0; kt < nkt; kt++) {
        if (kt + 1 < nkt) { do_copy((kt + 1) & 1, kt + 1); CP_COMMIT(); CP_WAIT1(); }
        else              { CP_WAIT0(); }
        __syncthreads();
        const uint32_t* ksm = asm_ + (kt & 1) * 8192;
        const uint32_t* vsm = ksm + 4096;

        float c[8][4];
        #pragma unroll
        for (int t = 0; t < 8; t++) { c[t][0] = c[t][1] = c[t][2] = c[t][3] = 0.f; }
        #pragma unroll
        for (int ks = 0; ks < 8; ks++) {
            #pragma unroll
            for (int t = 0; t < 8; t++) {
                uint2 kf = *(const uint2*)&ksm[((t * 8 + ks) * 32 + lane) * 2];
                MMA16816(c[t], qhi[ks], kf.x, kf.y);
                MMA16816(c[t], qlo[ks], kf.x, kf.y);
            }
        }

        float mxa = -1e30f, mxb = -1e30f;
        const bool need_mask = (kt * 64 + 63 > q0 + wid * 16);
        #pragma unroll
        for (int t = 0; t < 8; t++) {
            int k0 = kt * 64 + t * 8 + 2 * tig;
            float s0 = c[t][0] * scale, s1 = c[t][1] * scale;
            float s2 = c[t][2] * scale, s3 = c[t][3] * scale;
            if (need_mask) {
                if (k0 > row_a)     s0 = -1e30f;
                if (k0 + 1 > row_a) s1 = -1e30f;
                if (k0 > row_b)     s2 = -1e30f;
                if (k0 + 1 > row_b) s3 = -1e30f;
            }
            c[t][0] = s0; c[t][1] = s1; c[t][2] = s2; c[t][3] = s3;
            mxa = fmaxf(mxa, fmaxf(s0, s1));
            mxb = fmaxf(mxb, fmaxf(s2, s3));
        }
        mxa = fmaxf(mxa, __shfl_xor_sync(0xffffffffu, mxa, 1));
        mxa = fmaxf(mxa, __shfl_xor_sync(0xffffffffu, mxa, 2));
        mxb = fmaxf(mxb, __shfl_xor_sync(0xffffffffu, mxb, 1));
        mxb = fmaxf(mxb, __shfl_xor_sync(0xffffffffu, mxb, 2));

        float mna = fmaxf(ma, mxa), mnb = fmaxf(mb, mxb);
        float cra = __expf(ma - mna), crb = __expf(mb - mnb);
        ma = mna; mb = mnb; la *= cra; lb *= crb;
        #pragma unroll
        for (int t = 0; t < 16; t++) {
            o[t][0] *= cra; o[t][1] *= cra;
            o[t][2] *= crb; o[t][3] *= crb;
        }

        uint4 ahi[4], alo[4];
        #pragma unroll
        for (int k2 = 0; k2 < 4; k2++) {
            int t0 = 2 * k2, t1 = 2 * k2 + 1;
            float p0 = __expf(c[t0][0] - ma), p1 = __expf(c[t0][1] - ma);
            float p2 = __expf(c[t0][2] - mb), p3 = __expf(c[t0][3] - mb);
            float p4 = __expf(c[t1][0] - ma), p5 = __expf(c[t1][1] - ma);
            float p6 = __expf(c[t1][2] - mb), p7 = __expf(c[t1][3] - mb);
            la += p0 + p1 + p4 + p5;
            lb += p2 + p3 + p6 + p7;
            split2h(p0, p1, ahi[k2].x, alo[k2].x);
            split2h(p2, p3, ahi[k2].y, alo[k2].y);
            split2h(p4, p5, ahi[k2].z, alo[k2].z);
            split2h(p6, p7, ahi[k2].w, alo[k2].w);
        }

        #pragma unroll
        for (int k2 = 0; k2 < 4; k2++) {
            #pragma unroll
            for (int t2 = 0; t2 < 16; t2++) {
                uint2 vf = *(const uint2*)&vsm[((t2 * 4 + k2) * 32 + lane) * 2];
                MMA16816(o[t2], ahi[k2], vf.x, vf.y);
                MMA16816(o[t2], alo[k2], vf.x, vf.y);
            }
        }
        __syncthreads();
    }

    la += __shfl_xor_sync(0xffffffffu, la, 1);
    la += __shfl_xor_sync(0xffffffffu, la, 2);
    lb += __shfl_xor_sync(0xffffffffu, lb, 1);
    lb += __shfl_xor_sync(0xffffffffu, lb, 2);
    float ia = 1.f / la, ib = 1.f / lb;

    const int b = bh >> 4, nh = bh & 15;
    const int mt = b * 128 + ((q0 >> 4) + wid);
    #pragma unroll
    for (int t2 = 0; t2 < 16; t2++) {
        int kt2 = nh * 8 + (t2 >> 1);
        size_t base = (((size_t)mt * 128 + kt2) * 32 + lane) * 8 + 2 * (t2 & 1);
        uint32_t h, l;
        split2h(o[t2][0] * ia, o[t2][1] * ia, h, l);
        g_cf[base] = h;     g_cf[base + 4] = l;
        split2h(o[t2][2] * ib, o[t2][3] * ib, h, l);
        g_cf[base + 1] = h; g_cf[base + 5] = l;
    }
}

// ---------------------------------------------------------------------------
// kernel_launch
// ---------------------------------------------------------------------------
extern "C" void kernel_launch(void* const* d_in, const int* in_sizes, int n_in,
                              void* d_out, int out_size)
{
    const float* x    = (const float*)d_in[0];
    const float* wqkv = (const float*)d_in[2];
    const float* wo   = (const float*)d_in[3];

    float* qkv_p;
    uint32_t *xf_p, *cf_p, *wqkvf_p, *wof_p;
    cudaGetSymbolAddress((void**)&qkv_p, g_qkv);
    cudaGetSymbolAddress((void**)&xf_p, g_xf);
    cudaGetSymbolAddress((void**)&cf_p, g_cf);
    cudaGetSymbolAddress((void**)&wqkvf_p, g_wqkvf);
    cudaGetSymbolAddress((void**)&wof_p, g_wof);

    cudaFuncSetAttribute(gemm_frag, cudaFuncAttributeMaxDynamicSharedMemorySize, GEMM_SMEM);
    cudaFuncSetAttribute(attn_mma, cudaFuncAttributeMaxDynamicSharedMemorySize, ATTN_SMEM);

    trig_kernel<<<(S_ * 64 + 255) / 256, 256>>>();
    wfrag_kernel<<<dim3(H_ / 32, NQKV / 32), dim3(32, 8)>>>(wqkv, wqkvf_p, H_, NQKV);
    wfrag_kernel<<<dim3(H_ / 32, H_ / 32), dim3(32, 8)>>>(wo, wof_p, H_, H_);
    afrag_kernel<<<(M_ * H_ / 4) / 256, 256>>>(x, xf_p, M_, H_);

    gemm_frag<<<dim3(NQKV / 128, M_ / 128), 256, GEMM_SMEM>>>(xf_p, wqkvf_p, qkv_p, M_, NQKV, H_);
    prep_kernel<<<dim3(32, 32), 256>>>();
    attn_mma<<<dim3(S_ / 128, B_ * NH_), 256, ATTN_SMEM>>>();
    gemm_frag<<<dim3(H_ / 128, M_ / 128), 256, GEMM_SMEM>>>(cf_p, wof_p, (float*)d_out, M_, H_, H_);
}

// round 13
// speedup vs baseline: 1.5491x; 1.0188x over previous
#include <cuda_runtime.h>
#include <cuda_fp16.h>
#include <cstdint>
#include <math.h>

// Problem constants
#define B_   2
#define S_   2048
#define H_   2048
#define NH_  16
#define HD_  128
#define M_   (B_ * S_)      // 4096
#define NQKV (3 * H_)       // 6144

// ---------------------------------------------------------------------------
// Scratch (device globals — allocation-free per harness rules)
// ---------------------------------------------------------------------------
__device__ __align__(256) float g_qkv[(size_t)M_ * NQKV];
__device__ __align__(256) float g_cos[S_ * 64];
__device__ __align__(256) float g_sin[S_ * 64];
// attention fragment arrays: Q 2-term fp16 (8w), K/V single fp16 (2w)
__device__ __align__(256) uint32_t g_qf[(size_t)32 * 128 * 2048];
__device__ __align__(256) uint32_t g_kf[(size_t)32 * 32 * 4096];
__device__ __align__(256) uint32_t g_vf[(size_t)32 * 32 * 4096];
// GEMM fragment arrays: A 2-term fp16 (8w/lane/tile), B single fp16 (2w)
__device__ __align__(256) uint32_t g_xf[(size_t)M_ * H_];          // x A-frags
__device__ __align__(256) uint32_t g_cf[(size_t)M_ * H_];          // ctx A-frags
__device__ __align__(256) uint32_t g_wqkvf[(size_t)NQKV * H_ / 2]; // Wqkv B-frags
__device__ __align__(256) uint32_t g_wof[(size_t)H_ * H_ / 2];     // Wo B-frags

// ---------------------------------------------------------------------------
// Helpers: fp16 2-way split and single rounding
// ---------------------------------------------------------------------------
__device__ __forceinline__ void split2h(float a, float b, uint32_t& hi, uint32_t& lo) {
    __half2 h = __floats2half2_rn(a, b);
    float ra = a - __low2float(h);
    float rb = b - __high2float(h);
    __half2 l = __floats2half2_rn(ra, rb);
    hi = *(uint32_t*)&h;
    lo = *(uint32_t*)&l;
}
__device__ __forceinline__ uint32_t pack2h(float a, float b) {
    __half2 h = __floats2half2_rn(a, b);
    return *(uint32_t*)&h;
}
#define MMA16816(cr, a, b0r, b1r)                                             \
    asm volatile("mma.sync.aligned.m16n8k16.row.col.f32.f16.f16.f32 "         \
        "{%0,%1,%2,%3}, {%4,%5,%6,%7}, {%8,%9}, {%0,%1,%2,%3};"               \
        : "+f"((cr)[0]), "+f"((cr)[1]), "+f"((cr)[2]), "+f"((cr)[3])          \
        : "r"((a).x), "r"((a).y), "r"((a).z), "r"((a).w), "r"(b0r), "r"(b1r))

__device__ __forceinline__ uint32_t smem_u32(const void* p) {
    uint32_t a;
    asm("{ .reg .u64 t; cvta.to.shared.u64 t, %1; cvt.u32.u64 %0, t; }" : "=r"(a) : "l"(p));
    return a;
}
#define CP_ASYNC16(dst, src) \
    asm volatile("cp.async.cg.shared.global [%0], [%1], 16;" :: "r"(dst), "l"(src))
#define CP_COMMIT() asm volatile("cp.async.commit_group;" ::: "memory")
#define CP_WAIT1()  asm volatile("cp.async.wait_group 1;" ::: "memory")
#define CP_WAIT0()  asm volatile("cp.async.wait_group 0;" ::: "memory")

// ---------------------------------------------------------------------------
// RoPE trig table (fp32 phase to match jax, accurate trig)
// ---------------------------------------------------------------------------
__global__ void trig_kernel() {
    int idx = blockIdx.x * blockDim.x + threadIdx.x;
    if (idx >= S_ * 64) return;
    int s = idx >> 6, i = idx & 63;
    float invf = (float)pow(10000.0, -(double)i / 64.0);
    float th = (float)s * invf;
    g_cos[idx] = (float)cos((double)th);
    g_sin[idx] = (float)sin((double)th);
}

// ---------------------------------------------------------------------------
// Activation -> A-fragment slabs (layout as R10, fp16 2-term).
// ---------------------------------------------------------------------------
__global__ __launch_bounds__(256) void afrag_kernel(
    const float* __restrict__ A, uint32_t* __restrict__ AF, int M, int K)
{
    int idx = blockIdx.x * blockDim.x + threadIdx.x;
    int m = idx / (K >> 2), c4 = idx % (K >> 2);
    int k = 4 * c4;
    float4 v = *(const float4*)(A + (size_t)m * K + k);
    uint32_t h0, l0, h1, l1;
    split2h(v.x, v.y, h0, l0);
    split2h(v.z, v.w, h1, l1);
    int kt = k >> 4, kk = k & 15, tg = (kk & 7) >> 1, half_k = kk >> 3;
    int lane = (m & 7) * 4 + tg;
    int reg = ((m >> 3) & 1) + 2 * half_k;
    size_t base = (((size_t)(m >> 4) * (K >> 4) + kt) * 32 + lane) * 8 + reg;
    AF[base] = h0;     AF[base + 4] = l0;
    AF[base + 8] = h1; AF[base + 12] = l1;
}

// ---------------------------------------------------------------------------
// Weight W[K,N] -> B-fragment slabs, single fp16 term.
// ---------------------------------------------------------------------------
__global__ void wfrag_kernel(const float* __restrict__ W, uint32_t* __restrict__ BF,
                             int K, int N) {
    __shared__ float t[32][33];
    int k0 = blockIdx.x * 32, n0 = blockIdx.y * 32;
    int tx = threadIdx.x, ty = threadIdx.y;
    #pragma unroll
    for (int j = 0; j < 4; j++)
        t[ty + 8 * j][tx] = W[(size_t)(k0 + ty + 8 * j) * N + n0 + tx];
    __syncthreads();
    int id = ty * 32 + tx;
    #pragma unroll
    for (int u = 0; u < 2; u++) {
        int pid = id + 256 * u;
        int n_l = pid & 31, kp = pid >> 5;
        int k_l = 2 * kp;
        uint32_t h = pack2h(t[k_l][n_l], t[k_l + 1][n_l]);
        int n = n0 + n_l, k = k0 + k_l;
        int nt = n >> 3, gg = n & 7;
        int kt = k >> 4, kk = k & 15, reg = kk >> 3, tg = (kk & 7) >> 1;
        int lane = gg * 4 + tg;
        size_t w = (((size_t)nt * (K >> 4) + kt) * 32 + lane) * 2;
        BF[w + reg] = h;
    }
}

// ---------------------------------------------------------------------------
// Fragment GEMM: CTA 128x128, 8 warps 4x2, warp 32x64, 2 CTAs/SM.
// fp16 2-term. 3-stage cp.async ring, ONE __syncthreads per iteration.
// Stage = A 16KB + B 8KB = 24KB (6144 words); 3 stages = 72KB.
// ---------------------------------------------------------------------------
#define GEMM_SMEM 73728
__global__ __launch_bounds__(256, 2) void gemm_frag(
    const uint32_t* __restrict__ AF, const uint32_t* __restrict__ BF,
    float* __restrict__ C, int M, int N, int K)
{
    extern __shared__ uint32_t sh[];
    const uint32_t sb = smem_u32(sh);
    const int tid = threadIdx.x;
    const int wid = tid >> 5, lane = tid & 31;
    const int g = lane >> 2, tig = lane & 3;
    const int warp_m = wid >> 1, warp_n = wid & 1;
    const int mt0 = blockIdx.y * 8, nt0 = blockIdx.x * 16;
    const int KT = K >> 4;
    const int NIT = K >> 5;

    float c[2][8][4] = {};

    auto do_copy = [&](int st, int it) {
        const int kt0 = it * 2;
        uint32_t sbase = sb + st * 24576;
        #pragma unroll
        for (int u = 0; u < 4; u++) {
            int i = tid + 256 * u;
            int slab = i >> 6, within = i & 63;
            int mt_l = slab >> 1, kt_l = slab & 1;
            const uint32_t* src =
                AF + (((size_t)(mt0 + mt_l) * KT + kt0 + kt_l) * 256 + within * 4);
            CP_ASYNC16(sbase + (slab * 256 + within * 4) * 4, src);
        }
        #pragma unroll
        for (int u = 0; u < 2; u++) {
            int i = tid + 256 * u;
            int slab = i >> 4, within = i & 15;
            int nt_l = slab >> 1, kt_l = slab & 1;
            const uint32_t* src =
                BF + (((size_t)(nt0 + nt_l) * KT + kt0 + kt_l) * 64 + within * 4);
            CP_ASYNC16(sbase + 16384 + (slab * 64 + within * 4) * 4, src);
        }
    };

    do_copy(0, 0); CP_COMMIT();
    do_copy(1, 1); CP_COMMIT();

    int rs = 0, cs = 2;   // read stage, next copy stage
    for (int it = 0; it < NIT; it++) {
        if (it + 1 < NIT) CP_WAIT1(); else CP_WAIT0();
        __syncthreads();
        if (it + 2 < NIT) {
            do_copy(cs, it + 2); CP_COMMIT();
            if (++cs == 3) cs = 0;
        }

        const uint32_t* s = sh + rs * 6144;
        if (++rs == 3) rs = 0;
        #pragma unroll
        for (int tk = 0; tk < 2; tk++) {
            uint4 ahi[2], alo[2];
            #pragma unroll
            for (int i = 0; i < 2; i++) {
                int off = (((warp_m * 2 + i) * 2 + tk) * 32 + lane) * 8;
                ahi[i] = *(const uint4*)&s[off];
                alo[i] = *(const uint4*)&s[off + 4];
            }
            #pragma unroll
            for (int j = 0; j < 8; j++) {
                int off = 4096 + (((warp_n * 8 + j) * 2 + tk) * 32 + lane) * 2;
                uint2 bf = *(const uint2*)&s[off];
                #pragma unroll
                for (int i = 0; i < 2; i++) {
                    MMA16816(c[i][j], ahi[i], bf.x, bf.y);
                    MMA16816(c[i][j], alo[i], bf.x, bf.y);
                }
            }
        }
    }

    const int row0 = mt0 * 16, col0 = nt0 * 8;
    #pragma unroll
    for (int i = 0; i < 2; i++) {
        int r0 = row0 + (warp_m * 2 + i) * 16 + g;
        #pragma unroll
        for (int j = 0; j < 8; j++) {
            int cc = col0 + (warp_n * 8 + j) * 8 + tig * 2;
            *(float2*)(C + (size_t)r0 * N + cc)       = make_float2(c[i][j][0], c[i][j][1]);
            *(float2*)(C + (size_t)(r0 + 8) * N + cc) = make_float2(c[i][j][2], c[i][j][3]);
        }
    }
}

// ---------------------------------------------------------------------------
// Prep: qkv -> RoPE'd Q (2-term) / K,V (1-term) fp16 fragments (as R12).
// ---------------------------------------------------------------------------
__global__ __launch_bounds__(256) void prep_kernel() {
    const int st = blockIdx.x, bh = blockIdx.y;
    const int b = bh >> 4, nh = bh & 15;
    const int s0 = st * 64;
    const int tid = threadIdx.x;
    __shared__ float vsm[64 * 132];

    #pragma unroll
    for (int u = 0; u < 8; u++) {
        int i = tid + 256 * u;
        int r = i >> 5, dg = i & 31;
        int s = s0 + r;
        size_t base = (size_t)(b * S_ + s) * NQKV + nh * HD_;
        float2 qx = *(const float2*)&g_qkv[base + 2 * dg];
        float2 qy = *(const float2*)&g_qkv[base + 2 * dg + 64];
        float2 kx = *(const float2*)&g_qkv[base + H_ + 2 * dg];
        float2 ky = *(const float2*)&g_qkv[base + H_ + 2 * dg + 64];
        float c0 = g_cos[s * 64 + 2 * dg], c1 = g_cos[s * 64 + 2 * dg + 1];
        float n0 = g_sin[s * 64 + 2 * dg], n1 = g_sin[s * 64 + 2 * dg + 1];

        float qa0 = qx.x * c0 - qy.x * n0, qa1 = qx.y * c1 - qy.y * n1;
        float qb0 = qy.x * c0 + qx.x * n0, qb1 = qy.y * c1 + qx.y * n1;
        float ka0 = kx.x * c0 - ky.x * n0, ka1 = kx.y * c1 - ky.y * n1;
        float kb0 = ky.x * c0 + kx.x * n0, kb1 = ky.y * c1 + kx.y * n1;

        int mq = s >> 4, rr = s & 15;
        size_t qb_ = (size_t)(bh * 128 + mq) * 2048;
        int tl = (s >> 3) & 7, gk = s & 7;
        size_t kb_ = (size_t)(bh * 32 + st) * 4096 + (size_t)tl * 512;

        uint32_t h, l;
        {
            int p = dg, ks = p >> 3, pl = p & 7;
            int lane = (rr & 7) * 4 + (pl & 3);
            int reg = (rr >> 3) + 2 * (pl >> 2);
            split2h(qa0, qa1, h, l);
            size_t w = qb_ + (size_t)ks * 256 + lane * 8;
            g_qf[w + reg] = h; g_qf[w + 4 + reg] = l;
            int klane = gk * 4 + (pl & 3), kreg = pl >> 2;
            g_kf[kb_ + (size_t)ks * 64 + klane * 2 + kreg] = pack2h(ka0, ka1);
        }
        {
            int p = dg + 32, ks = p >> 3, pl = p & 7;
            int lane = (rr & 7) * 4 + (pl & 3);
            int reg = (rr >> 3) + 2 * (pl >> 2);
            split2h(qb0, qb1, h, l);
            size_t w = qb_ + (size_t)ks * 256 + lane * 8;
            g_qf[w + reg] = h; g_qf[w + 4 + reg] = l;
            int klane = gk * 4 + (pl & 3), kreg = pl >> 2;
            g_kf[kb_ + (size_t)ks * 64 + klane * 2 + kreg] = pack2h(kb0, kb1);
        }
    }

    #pragma unroll
    for (int u = 0; u < 8; u++) {
        int i = tid + 256 * u;
        int r = i >> 5, c4 = i & 31;
        size_t base = (size_t)(b * S_ + s0 + r) * NQKV + nh * HD_ + 2 * H_;
        float4 v = *(const float4*)&g_qkv[base + 4 * c4];
        float* d = &vsm[r * 132 + 4 * c4];
        d[0] = v.x; d[1] = v.y; d[2] = v.z; d[3] = v.w;
    }
    __syncthreads();

    {
        int kp = tid >> 3, nb = tid & 7;
        int ks2 = kp >> 3, tg2 = kp & 3, half = (kp >> 2) & 1;
        size_t vb_ = (size_t)(bh * 32 + st) * 4096;
        #pragma unroll
        for (int j = 0; j < 16; j++) {
            int n = nb + 8 * j;
            uint32_t h = pack2h(vsm[2 * kp * 132 + n], vsm[(2 * kp + 1) * 132 + n]);
            int lane = nb * 4 + tg2;
            g_vf[vb_ + ((size_t)(j * 4 + ks2) * 32 + lane) * 2 + half] = h;
        }
    }
}

// ---------------------------------------------------------------------------
// MMA flash attention, fp16, 3-stage cp.async ring, single sync per k-tile.
// Stage = K 16KB + V 16KB = 32KB (8192 words); 3 stages = 96KB.
// ---------------------------------------------------------------------------
#define ATTN_SMEM 98304
__global__ __launch_bounds__(256, 1) void attn_mma() {
    extern __shared__ uint32_t asm_[];

    const int bh = blockIdx.y;
    const int qt = (int)(gridDim.x - 1 - blockIdx.x);
    const int q0 = qt * 128;
    const int tid = threadIdx.x, wid = tid >> 5, lane = tid & 31;
    const int g = lane >> 2, tig = lane & 3;
    const uint32_t sb = smem_u32(asm_);

    uint4 qhi[8], qlo[8];
    {
        const uint32_t* qf = g_qf + (size_t)(bh * 128 + (q0 >> 4) + wid) * 2048;
        #pragma unroll
        for (int ks = 0; ks < 8; ks++) {
            const uint32_t* p = qf + (ks * 32 + lane) * 8;
            qhi[ks] = *(const uint4*)p;
            qlo[ks] = *(const uint4*)(p + 4);
        }
    }

    float o[16][4];
    #pragma unroll
    for (int t = 0; t < 16; t++) { o[t][0] = o[t][1] = o[t][2] = o[t][3] = 0.f; }
    float ma = -1e30f, mb = -1e30f, la = 0.f, lb = 0.f;
    const int row_a = q0 + wid * 16 + g;
    const int row_b = row_a + 8;
    const float scale = 0.08838834764831845f;

    const int nkt = (q0 + 128) >> 6;

    auto do_copy = [&](int st, int kt) {
        const uint4* gk = (const uint4*)(g_kf + (size_t)(bh * 32 + kt) * 4096);
        const uint4* gv = (const uint4*)(g_vf + (size_t)(bh * 32 + kt) * 4096);
        uint32_t base = sb + st * 32768;
        #pragma unroll
        for (int u = 0; u < 4; u++) {
            int i = tid + 256 * u;
            CP_ASYNC16(base + i * 16, gk + i);
            CP_ASYNC16(base + 16384 + i * 16, gv + i);
        }
    };

    do_copy(0, 0); CP_COMMIT();
    if (nkt > 1) { do_copy(1, 1); CP_COMMIT(); }

    int rs = 0, cs2 = 2;
    for (int kt = 0; kt < nkt; kt++) {
        if (kt + 1 < nkt) CP_WAIT1(); else CP_WAIT0();
        __syncthreads();
        if (kt + 2 < nkt) {
            do_copy(cs2, kt + 2); CP_COMMIT();
            if (++cs2 == 3) cs2 = 0;
        }
        const uint32_t* ksm = asm_ + rs * 8192;
        const uint32_t* vsm = ksm + 4096;
        if (++rs == 3) rs = 0;

        float c[8][4];
        #pragma unroll
        for (int t = 0; t < 8; t++) { c[t][0] = c[t][1] = c[t][2] = c[t][3] = 0.f; }
        #pragma unroll
        for (int ks = 0; ks < 8; ks++) {
            #pragma unroll
            for (int t = 0; t < 8; t++) {
                uint2 kf = *(const uint2*)&ksm[((t * 8 + ks) * 32 + lane) * 2];
                MMA16816(c[t], qhi[ks], kf.x, kf.y);
                MMA16816(c[t], qlo[ks], kf.x, kf.y);
            }
        }

        float mxa = -1e30f, mxb = -1e30f;
        const bool need_mask = (kt * 64 + 63 > q0 + wid * 16);
        #pragma unroll
        for (int t = 0; t < 8; t++) {
            int k0 = kt * 64 + t * 8 + 2 * tig;
            float s0 = c[t][0] * scale, s1 = c[t][1] * scale;
            float s2 = c[t][2] * scale, s3 = c[t][3] * scale;
            if (need_mask) {
                if (k0 > row_a)     s0 = -1e30f;
                if (k0 + 1 > row_a) s1 = -1e30f;
                if (k0 > row_b)     s2 = -1e30f;
                if (k0 + 1 > row_b) s3 = -1e30f;
            }
            c[t][0] = s0; c[t][1] = s1; c[t][2] = s2; c[t][3] = s3;
            mxa = fmaxf(mxa, fmaxf(s0, s1));
            mxb = fmaxf(mxb, fmaxf(s2, s3));
        }
        mxa = fmaxf(mxa, __shfl_xor_sync(0xffffffffu, mxa, 1));
        mxa = fmaxf(mxa, __shfl_xor_sync(0xffffffffu, mxa, 2));
        mxb = fmaxf(mxb, __shfl_xor_sync(0xffffffffu, mxb, 1));
        mxb = fmaxf(mxb, __shfl_xor_sync(0xffffffffu, mxb, 2));

        float mna = fmaxf(ma, mxa), mnb = fmaxf(mb, mxb);
        float cra = __expf(ma - mna), crb = __expf(mb - mnb);
        ma = mna; mb = mnb; la *= cra; lb *= crb;
        #pragma unroll
        for (int t = 0; t < 16; t++) {
            o[t][0] *= cra; o[t][1] *= cra;
            o[t][2] *= crb; o[t][3] *= crb;
        }

        uint4 ahi[4], alo[4];
        #pragma unroll
        for (int k2 = 0; k2 < 4; k2++) {
            int t0 = 2 * k2, t1 = 2 * k2 + 1;
            float p0 = __expf(c[t0][0] - ma), p1 = __expf(c[t0][1] - ma);
            float p2 = __expf(c[t0][2] - mb), p3 = __expf(c[t0][3] - mb);
            float p4 = __expf(c[t1][0] - ma), p5 = __expf(c[t1][1] - ma);
            float p6 = __expf(c[t1][2] - mb), p7 = __expf(c[t1][3] - mb);
            la += p0 + p1 + p4 + p5;
            lb += p2 + p3 + p6 + p7;
            split2h(p0, p1, ahi[k2].x, alo[k2].x);
            split2h(p2, p3, ahi[k2].y, alo[k2].y);
            split2h(p4, p5, ahi[k2].z, alo[k2].z);
            split2h(p6, p7, ahi[k2].w, alo[k2].w);
        }

        #pragma unroll
        for (int k2 = 0; k2 < 4; k2++) {
            #pragma unroll
            for (int t2 = 0; t2 < 16; t2++) {
                uint2 vf = *(const uint2*)&vsm[((t2 * 4 + k2) * 32 + lane) * 2];
                MMA16816(o[t2], ahi[k2], vf.x, vf.y);
                MMA16816(o[t2], alo[k2], vf.x, vf.y);
            }
        }
    }

    la += __shfl_xor_sync(0xffffffffu, la, 1);
    la += __shfl_xor_sync(0xffffffffu, la, 2);
    lb += __shfl_xor_sync(0xffffffffu, lb, 1);
    lb += __shfl_xor_sync(0xffffffffu, lb, 2);
    float ia = 1.f / la, ib = 1.f / lb;

    const int b = bh >> 4, nh = bh & 15;
    const int mt = b * 128 + ((q0 >> 4) + wid);
    #pragma unroll
    for (int t2 = 0; t2 < 16; t2++) {
        int kt2 = nh * 8 + (t2 >> 1);
        size_t base = (((size_t)mt * 128 + kt2) * 32 + lane) * 8 + 2 * (t2 & 1);
        uint32_t h, l;
        split2h(o[t2][0] * ia, o[t2][1] * ia, h, l);
        g_cf[base] = h;     g_cf[base + 4] = l;
        split2h(o[t2][2] * ib, o[t2][3] * ib, h, l);
        g_cf[base + 1] = h; g_cf[base + 5] = l;
    }
}

// ---------------------------------------------------------------------------
// kernel_launch
// ---------------------------------------------------------------------------
extern "C" void kernel_launch(void* const* d_in, const int* in_sizes, int n_in,
                              void* d_out, int out_size)
{
    const float* x    = (const float*)d_in[0];
    const float* wqkv = (const float*)d_in[2];
    const float* wo   = (const float*)d_in[3];

    float* qkv_p;
    uint32_t *xf_p, *cf_p, *wqkvf_p, *wof_p;
    cudaGetSymbolAddress((void**)&qkv_p, g_qkv);
    cudaGetSymbolAddress((void**)&xf_p, g_xf);
    cudaGetSymbolAddress((void**)&cf_p, g_cf);
    cudaGetSymbolAddress((void**)&wqkvf_p, g_wqkvf);
    cudaGetSymbolAddress((void**)&wof_p, g_wof);

    cudaFuncSetAttribute(gemm_frag, cudaFuncAttributeMaxDynamicSharedMemorySize, GEMM_SMEM);
    cudaFuncSetAttribute(attn_mma, cudaFuncAttributeMaxDynamicSharedMemorySize, ATTN_SMEM);

    trig_kernel<<<(S_ * 64 + 255) / 256, 256>>>();
    wfrag_kernel<<<dim3(H_ / 32, NQKV / 32), dim3(32, 8)>>>(wqkv, wqkvf_p, H_, NQKV);
    wfrag_kernel<<<dim3(H_ / 32, H_ / 32), dim3(32, 8)>>>(wo, wof_p, H_, H_);
    afrag_kernel<<<(M_ * H_ / 4) / 256, 256>>>(x, xf_p, M_, H_);

    gemm_frag<<<dim3(NQKV / 128, M_ / 128), 256, GEMM_SMEM>>>(xf_p, wqkvf_p, qkv_p, M_, NQKV, H_);
    prep_kernel<<<dim3(32, 32), 256>>>();
    attn_mma<<<dim3(S_ / 128, B_ * NH_), 256, ATTN_SMEM>>>();
    gemm_frag<<<dim3(H_ / 128, M_ / 128), 256, GEMM_SMEM>>>(cf_p, wof_p, (float*)d_out, M_, H_, H_);
}

// round 14
// speedup vs baseline: 1.5506x; 1.0010x over previous
#include <cuda_runtime.h>
#include <cuda_fp16.h>
#include <cstdint>
#include <math.h>

// Problem constants
#define B_   2
#define S_   2048
#define H_   2048
#define NH_  16
#define HD_  128
#define M_   (B_ * S_)      // 4096
#define NQKV (3 * H_)       // 6144

// ---------------------------------------------------------------------------
// Scratch (device globals — allocation-free per harness rules)
// ---------------------------------------------------------------------------
__device__ __align__(256) float g_qkv[(size_t)M_ * NQKV];
__device__ __align__(256) float g_cos[S_ * 64];
__device__ __align__(256) float g_sin[S_ * 64];
// attention fragment arrays: Q 2-term fp16 (8w), K/V single fp16 (2w)
__device__ __align__(256) uint32_t g_qf[(size_t)32 * 128 * 2048];
__device__ __align__(256) uint32_t g_kf[(size_t)32 * 32 * 4096];
__device__ __align__(256) uint32_t g_vf[(size_t)32 * 32 * 4096];
// GEMM fragment arrays: A 2-term fp16 (8w/lane/tile), B single fp16 (2w)
__device__ __align__(256) uint32_t g_xf[(size_t)M_ * H_];          // x A-frags
__device__ __align__(256) uint32_t g_cf[(size_t)M_ * H_];          // ctx A-frags
__device__ __align__(256) uint32_t g_wqkvf[(size_t)NQKV * H_ / 2]; // Wqkv B-frags
__device__ __align__(256) uint32_t g_wof[(size_t)H_ * H_ / 2];     // Wo B-frags

// ---------------------------------------------------------------------------
// Helpers: fp16 2-way split and single rounding
// ---------------------------------------------------------------------------
__device__ __forceinline__ void split2h(float a, float b, uint32_t& hi, uint32_t& lo) {
    __half2 h = __floats2half2_rn(a, b);
    float ra = a - __low2float(h);
    float rb = b - __high2float(h);
    __half2 l = __floats2half2_rn(ra, rb);
    hi = *(uint32_t*)&h;
    lo = *(uint32_t*)&l;
}
__device__ __forceinline__ uint32_t pack2h(float a, float b) {
    __half2 h = __floats2half2_rn(a, b);
    return *(uint32_t*)&h;
}
#define MMA16816(cr, a, b0r, b1r)                                             \
    asm volatile("mma.sync.aligned.m16n8k16.row.col.f32.f16.f16.f32 "         \
        "{%0,%1,%2,%3}, {%4,%5,%6,%7}, {%8,%9}, {%0,%1,%2,%3};"               \
        : "+f"((cr)[0]), "+f"((cr)[1]), "+f"((cr)[2]), "+f"((cr)[3])          \
        : "r"((a).x), "r"((a).y), "r"((a).z), "r"((a).w), "r"(b0r), "r"(b1r))

__device__ __forceinline__ uint32_t smem_u32(const void* p) {
    uint32_t a;
    asm("{ .reg .u64 t; cvta.to.shared.u64 t, %1; cvt.u32.u64 %0, t; }" : "=r"(a) : "l"(p));
    return a;
}
#define CP_ASYNC16(dst, src) \
    asm volatile("cp.async.cg.shared.global [%0], [%1], 16;" :: "r"(dst), "l"(src))
#define CP_COMMIT() asm volatile("cp.async.commit_group;" ::: "memory")
#define CP_WAIT1()  asm volatile("cp.async.wait_group 1;" ::: "memory")
#define CP_WAIT0()  asm volatile("cp.async.wait_group 0;" ::: "memory")

// ---------------------------------------------------------------------------
// RoPE trig table (fp32 phase to match jax, accurate trig)
// ---------------------------------------------------------------------------
__global__ void trig_kernel() {
    int idx = blockIdx.x * blockDim.x + threadIdx.x;
    if (idx >= S_ * 64) return;
    int s = idx >> 6, i = idx & 63;
    float invf = (float)pow(10000.0, -(double)i / 64.0);
    float th = (float)s * invf;
    g_cos[idx] = (float)cos((double)th);
    g_sin[idx] = (float)sin((double)th);
}

// ---------------------------------------------------------------------------
// Activation -> A-fragment slabs (layout as R10, fp16 2-term).
// ---------------------------------------------------------------------------
__global__ __launch_bounds__(256) void afrag_kernel(
    const float* __restrict__ A, uint32_t* __restrict__ AF, int M, int K)
{
    int idx = blockIdx.x * blockDim.x + threadIdx.x;
    int m = idx / (K >> 2), c4 = idx % (K >> 2);
    int k = 4 * c4;
    float4 v = *(const float4*)(A + (size_t)m * K + k);
    uint32_t h0, l0, h1, l1;
    split2h(v.x, v.y, h0, l0);
    split2h(v.z, v.w, h1, l1);
    int kt = k >> 4, kk = k & 15, tg = (kk & 7) >> 1, half_k = kk >> 3;
    int lane = (m & 7) * 4 + tg;
    int reg = ((m >> 3) & 1) + 2 * half_k;
    size_t base = (((size_t)(m >> 4) * (K >> 4) + kt) * 32 + lane) * 8 + reg;
    AF[base] = h0;     AF[base + 4] = l0;
    AF[base + 8] = h1; AF[base + 12] = l1;
}

// ---------------------------------------------------------------------------
// Weight W[K,N] -> B-fragment slabs, single fp16 term.
// ---------------------------------------------------------------------------
__global__ void wfrag_kernel(const float* __restrict__ W, uint32_t* __restrict__ BF,
                             int K, int N) {
    __shared__ float t[32][33];
    int k0 = blockIdx.x * 32, n0 = blockIdx.y * 32;
    int tx = threadIdx.x, ty = threadIdx.y;
    #pragma unroll
    for (int j = 0; j < 4; j++)
        t[ty + 8 * j][tx] = W[(size_t)(k0 + ty + 8 * j) * N + n0 + tx];
    __syncthreads();
    int id = ty * 32 + tx;
    #pragma unroll
    for (int u = 0; u < 2; u++) {
        int pid = id + 256 * u;
        int n_l = pid & 31, kp = pid >> 5;
        int k_l = 2 * kp;
        uint32_t h = pack2h(t[k_l][n_l], t[k_l + 1][n_l]);
        int n = n0 + n_l, k = k0 + k_l;
        int nt = n >> 3, gg = n & 7;
        int kt = k >> 4, kk = k & 15, reg = kk >> 3, tg = (kk & 7) >> 1;
        int lane = gg * 4 + tg;
        size_t w = (((size_t)nt * (K >> 4) + kt) * 32 + lane) * 2;
        BF[w + reg] = h;
    }
}

// ---------------------------------------------------------------------------
// Fragment GEMM: CTA 128x128, 8 warps 4x2, warp 32x64, 2 CTAs/SM.
// fp16 2-term. 3-stage cp.async ring, ONE __syncthreads per iteration.
// Stage = A 16KB + B 8KB = 24KB (6144 words); 3 stages = 72KB.
// ---------------------------------------------------------------------------
#define GEMM_SMEM 73728
__global__ __launch_bounds__(256, 2) void gemm_frag(
    const uint32_t* __restrict__ AF, const uint32_t* __restrict__ BF,
    float* __restrict__ C, int M, int N, int K)
{
    extern __shared__ uint32_t sh[];
    const uint32_t sb = smem_u32(sh);
    const int tid = threadIdx.x;
    const int wid = tid >> 5, lane = tid & 31;
    const int g = lane >> 2, tig = lane & 3;
    const int warp_m = wid >> 1, warp_n = wid & 1;
    const int mt0 = blockIdx.y * 8, nt0 = blockIdx.x * 16;
    const int KT = K >> 4;
    const int NIT = K >> 5;

    float c[2][8][4] = {};

    auto do_copy = [&](int st, int it) {
        const int kt0 = it * 2;
        uint32_t sbase = sb + st * 24576;
        #pragma unroll
        for (int u = 0; u < 4; u++) {
            int i = tid + 256 * u;
            int slab = i >> 6, within = i & 63;
            int mt_l = slab >> 1, kt_l = slab & 1;
            const uint32_t* src =
                AF + (((size_t)(mt0 + mt_l) * KT + kt0 + kt_l) * 256 + within * 4);
            CP_ASYNC16(sbase + (slab * 256 + within * 4) * 4, src);
        }
        #pragma unroll
        for (int u = 0; u < 2; u++) {
            int i = tid + 256 * u;
            int slab = i >> 4, within = i & 15;
            int nt_l = slab >> 1, kt_l = slab & 1;
            const uint32_t* src =
                BF + (((size_t)(nt0 + nt_l) * KT + kt0 + kt_l) * 64 + within * 4);
            CP_ASYNC16(sbase + 16384 + (slab * 64 + within * 4) * 4, src);
        }
    };

    do_copy(0, 0); CP_COMMIT();
    do_copy(1, 1); CP_COMMIT();

    int rs = 0, cs = 2;   // read stage, next copy stage
    for (int it = 0; it < NIT; it++) {
        if (it + 1 < NIT) CP_WAIT1(); else CP_WAIT0();
        __syncthreads();
        if (it + 2 < NIT) {
            do_copy(cs, it + 2); CP_COMMIT();
            if (++cs == 3) cs = 0;
        }

        const uint32_t* s = sh + rs * 6144;
        if (++rs == 3) rs = 0;
        #pragma unroll
        for (int tk = 0; tk < 2; tk++) {
            uint4 ahi[2], alo[2];
            #pragma unroll
            for (int i = 0; i < 2; i++) {
                int off = (((warp_m * 2 + i) * 2 + tk) * 32 + lane) * 8;
                ahi[i] = *(const uint4*)&s[off];
                alo[i] = *(const uint4*)&s[off + 4];
            }
            #pragma unroll
            for (int j = 0; j < 8; j++) {
                int off = 4096 + (((warp_n * 8 + j) * 2 + tk) * 32 + lane) * 2;
                uint2 bf = *(const uint2*)&s[off];
                #pragma unroll
                for (int i = 0; i < 2; i++) {
                    MMA16816(c[i][j], ahi[i], bf.x, bf.y);
                    MMA16816(c[i][j], alo[i], bf.x, bf.y);
                }
            }
        }
    }

    const int row0 = mt0 * 16, col0 = nt0 * 8;
    #pragma unroll
    for (int i = 0; i < 2; i++) {
        int r0 = row0 + (warp_m * 2 + i) * 16 + g;
        #pragma unroll
        for (int j = 0; j < 8; j++) {
            int cc = col0 + (warp_n * 8 + j) * 8 + tig * 2;
            *(float2*)(C + (size_t)r0 * N + cc)       = make_float2(c[i][j][0], c[i][j][1]);
            *(float2*)(C + (size_t)(r0 + 8) * N + cc) = make_float2(c[i][j][2], c[i][j][3]);
        }
    }
}

// ---------------------------------------------------------------------------
// Prep: qkv -> RoPE'd Q (2-term) / K,V (1-term) fp16 fragments (as R12).
// ---------------------------------------------------------------------------
__global__ __launch_bounds__(256) void prep_kernel() {
    const int st = blockIdx.x, bh = blockIdx.y;
    const int b = bh >> 4, nh = bh & 15;
    const int s0 = st * 64;
    const int tid = threadIdx.x;
    __shared__ float vsm[64 * 132];

    #pragma unroll
    for (int u = 0; u < 8; u++) {
        int i = tid + 256 * u;
        int r = i >> 5, dg = i & 31;
        int s = s0 + r;
        size_t base = (size_t)(b * S_ + s) * NQKV + nh * HD_;
        float2 qx = *(const float2*)&g_qkv[base + 2 * dg];
        float2 qy = *(const float2*)&g_qkv[base + 2 * dg + 64];
        float2 kx = *(const float2*)&g_qkv[base + H_ + 2 * dg];
        float2 ky = *(const float2*)&g_qkv[base + H_ + 2 * dg + 64];
        float c0 = g_cos[s * 64 + 2 * dg], c1 = g_cos[s * 64 + 2 * dg + 1];
        float n0 = g_sin[s * 64 + 2 * dg], n1 = g_sin[s * 64 + 2 * dg + 1];

        float qa0 = qx.x * c0 - qy.x * n0, qa1 = qx.y * c1 - qy.y * n1;
        float qb0 = qy.x * c0 + qx.x * n0, qb1 = qy.y * c1 + qx.y * n1;
        float ka0 = kx.x * c0 - ky.x * n0, ka1 = kx.y * c1 - ky.y * n1;
        float kb0 = ky.x * c0 + kx.x * n0, kb1 = ky.y * c1 + kx.y * n1;

        int mq = s >> 4, rr = s & 15;
        size_t qb_ = (size_t)(bh * 128 + mq) * 2048;
        int tl = (s >> 3) & 7, gk = s & 7;
        size_t kb_ = (size_t)(bh * 32 + st) * 4096 + (size_t)tl * 512;

        uint32_t h, l;
        {
            int p = dg, ks = p >> 3, pl = p & 7;
            int lane = (rr & 7) * 4 + (pl & 3);
            int reg = (rr >> 3) + 2 * (pl >> 2);
            split2h(qa0, qa1, h, l);
            size_t w = qb_ + (size_t)ks * 256 + lane * 8;
            g_qf[w + reg] = h; g_qf[w + 4 + reg] = l;
            int klane = gk * 4 + (pl & 3), kreg = pl >> 2;
            g_kf[kb_ + (size_t)ks * 64 + klane * 2 + kreg] = pack2h(ka0, ka1);
        }
        {
            int p = dg + 32, ks = p >> 3, pl = p & 7;
            int lane = (rr & 7) * 4 + (pl & 3);
            int reg = (rr >> 3) + 2 * (pl >> 2);
            split2h(qb0, qb1, h, l);
            size_t w = qb_ + (size_t)ks * 256 + lane * 8;
            g_qf[w + reg] = h; g_qf[w + 4 + reg] = l;
            int klane = gk * 4 + (pl & 3), kreg = pl >> 2;
            g_kf[kb_ + (size_t)ks * 64 + klane * 2 + kreg] = pack2h(kb0, kb1);
        }
    }

    #pragma unroll
    for (int u = 0; u < 8; u++) {
        int i = tid + 256 * u;
        int r = i >> 5, c4 = i & 31;
        size_t base = (size_t)(b * S_ + s0 + r) * NQKV + nh * HD_ + 2 * H_;
        float4 v = *(const float4*)&g_qkv[base + 4 * c4];
        float* d = &vsm[r * 132 + 4 * c4];
        d[0] = v.x; d[1] = v.y; d[2] = v.z; d[3] = v.w;
    }
    __syncthreads();

    {
        int kp = tid >> 3, nb = tid & 7;
        int ks2 = kp >> 3, tg2 = kp & 3, half = (kp >> 2) & 1;
        size_t vb_ = (size_t)(bh * 32 + st) * 4096;
        #pragma unroll
        for (int j = 0; j < 16; j++) {
            int n = nb + 8 * j;
            uint32_t h = pack2h(vsm[2 * kp * 132 + n], vsm[(2 * kp + 1) * 132 + n]);
            int lane = nb * 4 + tg2;
            g_vf[vb_ + ((size_t)(j * 4 + ks2) * 32 + lane) * 2 + half] = h;
        }
    }
}

// ---------------------------------------------------------------------------
// MMA flash attention, fp16, 3-stage cp.async ring, single sync per k-tile.
// Stage = K 16KB + V 16KB = 32KB (8192 words); 3 stages = 96KB.
// ---------------------------------------------------------------------------
#define ATTN_SMEM 98304
__global__ __launch_bounds__(256, 1) void attn_mma() {
    extern __shared__ uint32_t asm_[];

    const int bh = blockIdx.y;
    const int qt = (int)(gridDim.x - 1 - blockIdx.x);
    const int q0 = qt * 128;
    const int tid = threadIdx.x, wid = tid >> 5, lane = tid & 31;
    const int g = lane >> 2, tig = lane & 3;
    const uint32_t sb = smem_u32(asm_);

    uint4 qhi[8], qlo[8];
    {
        const uint32_t* qf = g_qf + (size_t)(bh * 128 + (q0 >> 4) + wid) * 2048;
        #pragma unroll
        for (int ks = 0; ks < 8; ks++) {
            const uint32_t* p = qf + (ks * 32 + lane) * 8;
            qhi[ks] = *(const uint4*)p;
            qlo[ks] = *(const uint4*)(p + 4);
        }
    }

    float o[16][4];
    #pragma unroll
    for (int t = 0; t < 16; t++) { o[t][0] = o[t][1] = o[t][2] = o[t][3] = 0.f; }
    float ma = -1e30f, mb = -1e30f, la = 0.f, lb = 0.f;
    const int row_a = q0 + wid * 16 + g;
    const int row_b = row_a + 8;
    const float scale = 0.08838834764831845f;

    const int nkt = (q0 + 128) >> 6;

    auto do_copy = [&](int st, int kt) {
        const uint4* gk = (const uint4*)(g_kf + (size_t)(bh * 32 + kt) * 4096);
        const uint4* gv = (const uint4*)(g_vf + (size_t)(bh * 32 + kt) * 4096);
        uint32_t base = sb + st * 32768;
        #pragma unroll
        for (int u = 0; u < 4; u++) {
            int i = tid + 256 * u;
            CP_ASYNC16(base + i * 16, gk + i);
            CP_ASYNC16(base + 16384 + i * 16, gv + i);
        }
    };

    do_copy(0, 0); CP_COMMIT();
    if (nkt > 1) { do_copy(1, 1); CP_COMMIT(); }

    int rs = 0, cs2 = 2;
    for (int kt = 0; kt < nkt; kt++) {
        if (kt + 1 < nkt) CP_WAIT1(); else CP_WAIT0();
        __syncthreads();
        if (kt + 2 < nkt) {
            do_copy(cs2, kt + 2); CP_COMMIT();
            if (++cs2 == 3) cs2 = 0;
        }
        const uint32_t* ksm = asm_ + rs * 8192;
        const uint32_t* vsm = ksm + 4096;
        if (++rs == 3) rs = 0;

        float c[8][4];
        #pragma unroll
        for (int t = 0; t < 8; t++) { c[t][0] = c[t][1] = c[t][2] = c[t][3] = 0.f; }
        #pragma unroll
        for (int ks = 0; ks < 8; ks++) {
            #pragma unroll
            for (int t = 0; t < 8; t++) {
                uint2 kf = *(const uint2*)&ksm[((t * 8 + ks) * 32 + lane) * 2];
                MMA16816(c[t], qhi[ks], kf.x, kf.y);
                MMA16816(c[t], qlo[ks], kf.x, kf.y);
            }
        }

        float mxa = -1e30f, mxb = -1e30f;
        const bool need_mask = (kt * 64 + 63 > q0 + wid * 16);
        #pragma unroll
        for (int t = 0; t < 8; t++) {
            int k0 = kt * 64 + t * 8 + 2 * tig;
            float s0 = c[t][0] * scale, s1 = c[t][1] * scale;
            float s2 = c[t][2] * scale, s3 = c[t][3] * scale;
            if (need_mask) {
                if (k0 > row_a)     s0 = -1e30f;
                if (k0 + 1 > row_a) s1 = -1e30f;
                if (k0 > row_b)     s2 = -1e30f;
                if (k0 + 1 > row_b) s3 = -1e30f;
            }
            c[t][0] = s0; c[t][1] = s1; c[t][2] = s2; c[t][3] = s3;
            mxa = fmaxf(mxa, fmaxf(s0, s1));
            mxb = fmaxf(mxb, fmaxf(s2, s3));
        }
        mxa = fmaxf(mxa, __shfl_xor_sync(0xffffffffu, mxa, 1));
        mxa = fmaxf(mxa, __shfl_xor_sync(0xffffffffu, mxa, 2));
        mxb = fmaxf(mxb, __shfl_xor_sync(0xffffffffu, mxb, 1));
        mxb = fmaxf(mxb, __shfl_xor_sync(0xffffffffu, mxb, 2));

        float mna = fmaxf(ma, mxa), mnb = fmaxf(mb, mxb);
        float cra = __expf(ma - mna), crb = __expf(mb - mnb);
        ma = mna; mb = mnb; la *= cra; lb *= crb;
        #pragma unroll
        for (int t = 0; t < 16; t++) {
            o[t][0] *= cra; o[t][1] *= cra;
            o[t][2] *= crb; o[t][3] *= crb;
        }

        uint4 ahi[4], alo[4];
        #pragma unroll
        for (int k2 = 0; k2 < 4; k2++) {
            int t0 = 2 * k2, t1 = 2 * k2 + 1;
            float p0 = __expf(c[t0][0] - ma), p1 = __expf(c[t0][1] - ma);
            float p2 = __expf(c[t0][2] - mb), p3 = __expf(c[t0][3] - mb);
            float p4 = __expf(c[t1][0] - ma), p5 = __expf(c[t1][1] - ma);
            float p6 = __expf(c[t1][2] - mb), p7 = __expf(c[t1][3] - mb);
            la += p0 + p1 + p4 + p5;
            lb += p2 + p3 + p6 + p7;
            split2h(p0, p1, ahi[k2].x, alo[k2].x);
            split2h(p2, p3, ahi[k2].y, alo[k2].y);
            split2h(p4, p5, ahi[k2].z, alo[k2].z);
            split2h(p6, p7, ahi[k2].w, alo[k2].w);
        }

        #pragma unroll
        for (int k2 = 0; k2 < 4; k2++) {
            #pragma unroll
            for (int t2 = 0; t2 < 16; t2++) {
                uint2 vf = *(const uint2*)&vsm[((t2 * 4 + k2) * 32 + lane) * 2];
                MMA16816(o[t2], ahi[k2], vf.x, vf.y);
                MMA16816(o[t2], alo[k2], vf.x, vf.y);
            }
        }
    }

    la += __shfl_xor_sync(0xffffffffu, la, 1);
    la += __shfl_xor_sync(0xffffffffu, la, 2);
    lb += __shfl_xor_sync(0xffffffffu, lb, 1);
    lb += __shfl_xor_sync(0xffffffffu, lb, 2);
    float ia = 1.f / la, ib = 1.f / lb;

    const int b = bh >> 4, nh = bh & 15;
    const int mt = b * 128 + ((q0 >> 4) + wid);
    #pragma unroll
    for (int t2 = 0; t2 < 16; t2++) {
        int kt2 = nh * 8 + (t2 >> 1);
        size_t base = (((size_t)mt * 128 + kt2) * 32 + lane) * 8 + 2 * (t2 & 1);
        uint32_t h, l;
        split2h(o[t2][0] * ia, o[t2][1] * ia, h, l);
        g_cf[base] = h;     g_cf[base + 4] = l;
        split2h(o[t2][2] * ib, o[t2][3] * ib, h, l);
        g_cf[base + 1] = h; g_cf[base + 5] = l;
    }
}

// ---------------------------------------------------------------------------
// kernel_launch
// ---------------------------------------------------------------------------
extern "C" void kernel_launch(void* const* d_in, const int* in_sizes, int n_in,
                              void* d_out, int out_size)
{
    const float* x    = (const float*)d_in[0];
    const float* wqkv = (const float*)d_in[2];
    const float* wo   = (const float*)d_in[3];

    float* qkv_p;
    uint32_t *xf_p, *cf_p, *wqkvf_p, *wof_p;
    cudaGetSymbolAddress((void**)&qkv_p, g_qkv);
    cudaGetSymbolAddress((void**)&xf_p, g_xf);
    cudaGetSymbolAddress((void**)&cf_p, g_cf);
    cudaGetSymbolAddress((void**)&wqkvf_p, g_wqkvf);
    cudaGetSymbolAddress((void**)&wof_p, g_wof);

    cudaFuncSetAttribute(gemm_frag, cudaFuncAttributeMaxDynamicSharedMemorySize, GEMM_SMEM);
    cudaFuncSetAttribute(attn_mma, cudaFuncAttributeMaxDynamicSharedMemorySize, ATTN_SMEM);

    trig_kernel<<<(S_ * 64 + 255) / 256, 256>>>();
    wfrag_kernel<<<dim3(H_ / 32, NQKV / 32), dim3(32, 8)>>>(wqkv, wqkvf_p, H_, NQKV);
    wfrag_kernel<<<dim3(H_ / 32, H_ / 32), dim3(32, 8)>>>(wo, wof_p, H_, H_);
    afrag_kernel<<<(M_ * H_ / 4) / 256, 256>>>(x, xf_p, M_, H_);

    gemm_frag<<<dim3(NQKV / 128, M_ / 128), 256, GEMM_SMEM>>>(xf_p, wqkvf_p, qkv_p, M_, NQKV, H_);
    prep_kernel<<<dim3(32, 32), 256>>>();
    attn_mma<<<dim3(S_ / 128, B_ * NH_), 256, ATTN_SMEM>>>();
    gemm_frag<<<dim3(H_ / 128, M_ / 128), 256, GEMM_SMEM>>>(cf_p, wof_p, (float*)d_out, M_, H_, H_);
}

// round 15
// speedup vs baseline: 1.5517x; 1.0007x over previous
#include <cuda_runtime.h>
#include <cuda_fp16.h>
#include <cstdint>
#include <math.h>

// Problem constants
#define B_   2
#define S_   2048
#define H_   2048
#define NH_  16
#define HD_  128
#define M_   (B_ * S_)      // 4096
#define NQKV (3 * H_)       // 6144

// ---------------------------------------------------------------------------
// Scratch (device globals — allocation-free per harness rules)
// ---------------------------------------------------------------------------
__device__ __align__(256) float g_qkv[(size_t)M_ * NQKV];
__device__ __align__(256) float g_cos[S_ * 64];
__device__ __align__(256) float g_sin[S_ * 64];
// attention fragment arrays: Q 2-term fp16 (8w), K/V single fp16 (2w)
__device__ __align__(256) uint32_t g_qf[(size_t)32 * 128 * 2048];
__device__ __align__(256) uint32_t g_kf[(size_t)32 * 32 * 4096];
__device__ __align__(256) uint32_t g_vf[(size_t)32 * 32 * 4096];
// GEMM fragment arrays: A 2-term fp16 (8w/lane/tile), B single fp16 (2w)
__device__ __align__(256) uint32_t g_xf[(size_t)M_ * H_];          // x A-frags
__device__ __align__(256) uint32_t g_cf[(size_t)M_ * H_];          // ctx A-frags
__device__ __align__(256) uint32_t g_wqkvf[(size_t)NQKV * H_ / 2]; // Wqkv B-frags
__device__ __align__(256) uint32_t g_wof[(size_t)H_ * H_ / 2];     // Wo B-frags

// ---------------------------------------------------------------------------
// Helpers: fp16 2-way split and single rounding
// ---------------------------------------------------------------------------
__device__ __forceinline__ void split2h(float a, float b, uint32_t& hi, uint32_t& lo) {
    __half2 h = __floats2half2_rn(a, b);
    float ra = a - __low2float(h);
    float rb = b - __high2float(h);
    __half2 l = __floats2half2_rn(ra, rb);
    hi = *(uint32_t*)&h;
    lo = *(uint32_t*)&l;
}
__device__ __forceinline__ uint32_t pack2h(float a, float b) {
    __half2 h = __floats2half2_rn(a, b);
    return *(uint32_t*)&h;
}
#define MMA16816(cr, a, b0r, b1r)                                             \
    asm volatile("mma.sync.aligned.m16n8k16.row.col.f32.f16.f16.f32 "         \
        "{%0,%1,%2,%3}, {%4,%5,%6,%7}, {%8,%9}, {%0,%1,%2,%3};"               \
        : "+f"((cr)[0]), "+f"((cr)[1]), "+f"((cr)[2]), "+f"((cr)[3])          \
        : "r"((a).x), "r"((a).y), "r"((a).z), "r"((a).w), "r"(b0r), "r"(b1r))

__device__ __forceinline__ uint32_t smem_u32(const void* p) {
    uint32_t a;
    asm("{ .reg .u64 t; cvta.to.shared.u64 t, %1; cvt.u32.u64 %0, t; }" : "=r"(a) : "l"(p));
    return a;
}
#define CP_ASYNC16(dst, src) \
    asm volatile("cp.async.cg.shared.global [%0], [%1], 16;" :: "r"(dst), "l"(src))
#define CP_COMMIT() asm volatile("cp.async.commit_group;" ::: "memory")
#define CP_WAIT1()  asm volatile("cp.async.wait_group 1;" ::: "memory")
#define CP_WAIT0()  asm volatile("cp.async.wait_group 0;" ::: "memory")

// ---------------------------------------------------------------------------
// RoPE trig table (fp32 phase to match jax, accurate trig)
// ---------------------------------------------------------------------------
__global__ void trig_kernel() {
    int idx = blockIdx.x * blockDim.x + threadIdx.x;
    if (idx >= S_ * 64) return;
    int s = idx >> 6, i = idx & 63;
    float invf = (float)pow(10000.0, -(double)i / 64.0);
    float th = (float)s * invf;
    g_cos[idx] = (float)cos((double)th);
    g_sin[idx] = (float)sin((double)th);
}

// ---------------------------------------------------------------------------
// Activation -> A-fragment slabs (layout as R10, fp16 2-term).
// ---------------------------------------------------------------------------
__global__ __launch_bounds__(256) void afrag_kernel(
    const float* __restrict__ A, uint32_t* __restrict__ AF, int M, int K)
{
    int idx = blockIdx.x * blockDim.x + threadIdx.x;
    int m = idx / (K >> 2), c4 = idx % (K >> 2);
    int k = 4 * c4;
    float4 v = *(const float4*)(A + (size_t)m * K + k);
    uint32_t h0, l0, h1, l1;
    split2h(v.x, v.y, h0, l0);
    split2h(v.z, v.w, h1, l1);
    int kt = k >> 4, kk = k & 15, tg = (kk & 7) >> 1, half_k = kk >> 3;
    int lane = (m & 7) * 4 + tg;
    int reg = ((m >> 3) & 1) + 2 * half_k;
    size_t base = (((size_t)(m >> 4) * (K >> 4) + kt) * 32 + lane) * 8 + reg;
    AF[base] = h0;     AF[base + 4] = l0;
    AF[base + 8] = h1; AF[base + 12] = l1;
}

// ---------------------------------------------------------------------------
// Weight W[K,N] -> B-fragment slabs, single fp16 term.
// ---------------------------------------------------------------------------
__global__ void wfrag_kernel(const float* __restrict__ W, uint32_t* __restrict__ BF,
                             int K, int N) {
    __shared__ float t[32][33];
    int k0 = blockIdx.x * 32, n0 = blockIdx.y * 32;
    int tx = threadIdx.x, ty = threadIdx.y;
    #pragma unroll
    for (int j = 0; j < 4; j++)
        t[ty + 8 * j][tx] = W[(size_t)(k0 + ty + 8 * j) * N + n0 + tx];
    __syncthreads();
    int id = ty * 32 + tx;
    #pragma unroll
    for (int u = 0; u < 2; u++) {
        int pid = id + 256 * u;
        int n_l = pid & 31, kp = pid >> 5;
        int k_l = 2 * kp;
        uint32_t h = pack2h(t[k_l][n_l], t[k_l + 1][n_l]);
        int n = n0 + n_l, k = k0 + k_l;
        int nt = n >> 3, gg = n & 7;
        int kt = k >> 4, kk = k & 15, reg = kk >> 3, tg = (kk & 7) >> 1;
        int lane = gg * 4 + tg;
        size_t w = (((size_t)nt * (K >> 4) + kt) * 32 + lane) * 2;
        BF[w + reg] = h;
    }
}

// ---------------------------------------------------------------------------
// Fragment GEMM: CTA 128x128, 8 warps 4x2, warp 32x64, 2 CTAs/SM.
// fp16 2-term. 3-stage cp.async ring, ONE __syncthreads per iteration.
// Stage = A 16KB + B 8KB = 24KB (6144 words); 3 stages = 72KB.
// ---------------------------------------------------------------------------
#define GEMM_SMEM 73728
__global__ __launch_bounds__(256, 2) void gemm_frag(
    const uint32_t* __restrict__ AF, const uint32_t* __restrict__ BF,
    float* __restrict__ C, int M, int N, int K)
{
    extern __shared__ uint32_t sh[];
    const uint32_t sb = smem_u32(sh);
    const int tid = threadIdx.x;
    const int wid = tid >> 5, lane = tid & 31;
    const int g = lane >> 2, tig = lane & 3;
    const int warp_m = wid >> 1, warp_n = wid & 1;
    const int mt0 = blockIdx.y * 8, nt0 = blockIdx.x * 16;
    const int KT = K >> 4;
    const int NIT = K >> 5;

    float c[2][8][4] = {};

    auto do_copy = [&](int st, int it) {
        const int kt0 = it * 2;
        uint32_t sbase = sb + st * 24576;
        #pragma unroll
        for (int u = 0; u < 4; u++) {
            int i = tid + 256 * u;
            int slab = i >> 6, within = i & 63;
            int mt_l = slab >> 1, kt_l = slab & 1;
            const uint32_t* src =
                AF + (((size_t)(mt0 + mt_l) * KT + kt0 + kt_l) * 256 + within * 4);
            CP_ASYNC16(sbase + (slab * 256 + within * 4) * 4, src);
        }
        #pragma unroll
        for (int u = 0; u < 2; u++) {
            int i = tid + 256 * u;
            int slab = i >> 4, within = i & 15;
            int nt_l = slab >> 1, kt_l = slab & 1;
            const uint32_t* src =
                BF + (((size_t)(nt0 + nt_l) * KT + kt0 + kt_l) * 64 + within * 4);
            CP_ASYNC16(sbase + 16384 + (slab * 64 + within * 4) * 4, src);
        }
    };

    do_copy(0, 0); CP_COMMIT();
    do_copy(1, 1); CP_COMMIT();

    int rs = 0, cs = 2;   // read stage, next copy stage
    for (int it = 0; it < NIT; it++) {
        if (it + 1 < NIT) CP_WAIT1(); else CP_WAIT0();
        __syncthreads();
        if (it + 2 < NIT) {
            do_copy(cs, it + 2); CP_COMMIT();
            if (++cs == 3) cs = 0;
        }

        const uint32_t* s = sh + rs * 6144;
        if (++rs == 3) rs = 0;
        #pragma unroll
        for (int tk = 0; tk < 2; tk++) {
            uint4 ahi[2], alo[2];
            #pragma unroll
            for (int i = 0; i < 2; i++) {
                int off = (((warp_m * 2 + i) * 2 + tk) * 32 + lane) * 8;
                ahi[i] = *(const uint4*)&s[off];
                alo[i] = *(const uint4*)&s[off + 4];
            }
            #pragma unroll
            for (int j = 0; j < 8; j++) {
                int off = 4096 + (((warp_n * 8 + j) * 2 + tk) * 32 + lane) * 2;
                uint2 bf = *(const uint2*)&s[off];
                #pragma unroll
                for (int i = 0; i < 2; i++) {
                    MMA16816(c[i][j], ahi[i], bf.x, bf.y);
                    MMA16816(c[i][j], alo[i], bf.x, bf.y);
                }
            }
        }
    }

    const int row0 = mt0 * 16, col0 = nt0 * 8;
    #pragma unroll
    for (int i = 0; i < 2; i++) {
        int r0 = row0 + (warp_m * 2 + i) * 16 + g;
        #pragma unroll
        for (int j = 0; j < 8; j++) {
            int cc = col0 + (warp_n * 8 + j) * 8 + tig * 2;
            *(float2*)(C + (size_t)r0 * N + cc)       = make_float2(c[i][j][0], c[i][j][1]);
            *(float2*)(C + (size_t)(r0 + 8) * N + cc) = make_float2(c[i][j][2], c[i][j][3]);
        }
    }
}

// ---------------------------------------------------------------------------
// Prep: qkv -> RoPE'd Q (2-term) / K,V (1-term) fp16 fragments (as R12).
// ---------------------------------------------------------------------------
__global__ __launch_bounds__(256) void prep_kernel() {
    const int st = blockIdx.x, bh = blockIdx.y;
    const int b = bh >> 4, nh = bh & 15;
    const int s0 = st * 64;
    const int tid = threadIdx.x;
    __shared__ float vsm[64 * 132];

    #pragma unroll
    for (int u = 0; u < 8; u++) {
        int i = tid + 256 * u;
        int r = i >> 5, dg = i & 31;
        int s = s0 + r;
        size_t base = (size_t)(b * S_ + s) * NQKV + nh * HD_;
        float2 qx = *(const float2*)&g_qkv[base + 2 * dg];
        float2 qy = *(const float2*)&g_qkv[base + 2 * dg + 64];
        float2 kx = *(const float2*)&g_qkv[base + H_ + 2 * dg];
        float2 ky = *(const float2*)&g_qkv[base + H_ + 2 * dg + 64];
        float c0 = g_cos[s * 64 + 2 * dg], c1 = g_cos[s * 64 + 2 * dg + 1];
        float n0 = g_sin[s * 64 + 2 * dg], n1 = g_sin[s * 64 + 2 * dg + 1];

        float qa0 = qx.x * c0 - qy.x * n0, qa1 = qx.y * c1 - qy.y * n1;
        float qb0 = qy.x * c0 + qx.x * n0, qb1 = qy.y * c1 + qx.y * n1;
        float ka0 = kx.x * c0 - ky.x * n0, ka1 = kx.y * c1 - ky.y * n1;
        float kb0 = ky.x * c0 + kx.x * n0, kb1 = ky.y * c1 + kx.y * n1;

        int mq = s >> 4, rr = s & 15;
        size_t qb_ = (size_t)(bh * 128 + mq) * 2048;
        int tl = (s >> 3) & 7, gk = s & 7;
        size_t kb_ = (size_t)(bh * 32 + st) * 4096 + (size_t)tl * 512;

        uint32_t h, l;
        {
            int p = dg, ks = p >> 3, pl = p & 7;
            int lane = (rr & 7) * 4 + (pl & 3);
            int reg = (rr >> 3) + 2 * (pl >> 2);
            split2h(qa0, qa1, h, l);
            size_t w = qb_ + (size_t)ks * 256 + lane * 8;
            g_qf[w + reg] = h; g_qf[w + 4 + reg] = l;
            int klane = gk * 4 + (pl & 3), kreg = pl >> 2;
            g_kf[kb_ + (size_t)ks * 64 + klane * 2 + kreg] = pack2h(ka0, ka1);
        }
        {
            int p = dg + 32, ks = p >> 3, pl = p & 7;
            int lane = (rr & 7) * 4 + (pl & 3);
            int reg = (rr >> 3) + 2 * (pl >> 2);
            split2h(qb0, qb1, h, l);
            size_t w = qb_ + (size_t)ks * 256 + lane * 8;
            g_qf[w + reg] = h; g_qf[w + 4 + reg] = l;
            int klane = gk * 4 + (pl & 3), kreg = pl >> 2;
            g_kf[kb_ + (size_t)ks * 64 + klane * 2 + kreg] = pack2h(kb0, kb1);
        }
    }

    #pragma unroll
    for (int u = 0; u < 8; u++) {
        int i = tid + 256 * u;
        int r = i >> 5, c4 = i & 31;
        size_t base = (size_t)(b * S_ + s0 + r) * NQKV + nh * HD_ + 2 * H_;
        float4 v = *(const float4*)&g_qkv[base + 4 * c4];
        float* d = &vsm[r * 132 + 4 * c4];
        d[0] = v.x; d[1] = v.y; d[2] = v.z; d[3] = v.w;
    }
    __syncthreads();

    {
        int kp = tid >> 3, nb = tid & 7;
        int ks2 = kp >> 3, tg2 = kp & 3, half = (kp >> 2) & 1;
        size_t vb_ = (size_t)(bh * 32 + st) * 4096;
        #pragma unroll
        for (int j = 0; j < 16; j++) {
            int n = nb + 8 * j;
            uint32_t h = pack2h(vsm[2 * kp * 132 + n], vsm[(2 * kp + 1) * 132 + n]);
            int lane = nb * 4 + tg2;
            g_vf[vb_ + ((size_t)(j * 4 + ks2) * 32 + lane) * 2 + half] = h;
        }
    }
}

// ---------------------------------------------------------------------------
// MMA flash attention, fp16, 3-stage cp.async ring, single sync per k-tile.
// Stage = K 16KB + V 16KB = 32KB (8192 words); 3 stages = 96KB.
// ---------------------------------------------------------------------------
#define ATTN_SMEM 98304
__global__ __launch_bounds__(256, 1) void attn_mma() {
    extern __shared__ uint32_t asm_[];

    const int bh = blockIdx.y;
    const int qt = (int)(gridDim.x - 1 - blockIdx.x);
    const int q0 = qt * 128;
    const int tid = threadIdx.x, wid = tid >> 5, lane = tid & 31;
    const int g = lane >> 2, tig = lane & 3;
    const uint32_t sb = smem_u32(asm_);

    uint4 qhi[8], qlo[8];
    {
        const uint32_t* qf = g_qf + (size_t)(bh * 128 + (q0 >> 4) + wid) * 2048;
        #pragma unroll
        for (int ks = 0; ks < 8; ks++) {
            const uint32_t* p = qf + (ks * 32 + lane) * 8;
            qhi[ks] = *(const uint4*)p;
            qlo[ks] = *(const uint4*)(p + 4);
        }
    }

    float o[16][4];
    #pragma unroll
    for (int t = 0; t < 16; t++) { o[t][0] = o[t][1] = o[t][2] = o[t][3] = 0.f; }
    float ma = -1e30f, mb = -1e30f, la = 0.f, lb = 0.f;
    const int row_a = q0 + wid * 16 + g;
    const int row_b = row_a + 8;
    const float scale = 0.08838834764831845f;

    const int nkt = (q0 + 128) >> 6;

    auto do_copy = [&](int st, int kt) {
        const uint4* gk = (const uint4*)(g_kf + (size_t)(bh * 32 + kt) * 4096);
        const uint4* gv = (const uint4*)(g_vf + (size_t)(bh * 32 + kt) * 4096);
        uint32_t base = sb + st * 32768;
        #pragma unroll
        for (int u = 0; u < 4; u++) {
            int i = tid + 256 * u;
            CP_ASYNC16(base + i * 16, gk + i);
            CP_ASYNC16(base + 16384 + i * 16, gv + i);
        }
    };

    do_copy(0, 0); CP_COMMIT();
    if (nkt > 1) { do_copy(1, 1); CP_COMMIT(); }

    int rs = 0, cs2 = 2;
    for (int kt = 0; kt < nkt; kt++) {
        if (kt + 1 < nkt) CP_WAIT1(); else CP_WAIT0();
        __syncthreads();
        if (kt + 2 < nkt) {
            do_copy(cs2, kt + 2); CP_COMMIT();
            if (++cs2 == 3) cs2 = 0;
        }
        const uint32_t* ksm = asm_ + rs * 8192;
        const uint32_t* vsm = ksm + 4096;
        if (++rs == 3) rs = 0;

        float c[8][4];
        #pragma unroll
        for (int t = 0; t < 8; t++) { c[t][0] = c[t][1] = c[t][2] = c[t][3] = 0.f; }
        #pragma unroll
        for (int ks = 0; ks < 8; ks++) {
            #pragma unroll
            for (int t = 0; t < 8; t++) {
                uint2 kf = *(const uint2*)&ksm[((t * 8 + ks) * 32 + lane) * 2];
                MMA16816(c[t], qhi[ks], kf.x, kf.y);
                MMA16816(c[t], qlo[ks], kf.x, kf.y);
            }
        }

        float mxa = -1e30f, mxb = -1e30f;
        const bool need_mask = (kt * 64 + 63 > q0 + wid * 16);
        #pragma unroll
        for (int t = 0; t < 8; t++) {
            int k0 = kt * 64 + t * 8 + 2 * tig;
            float s0 = c[t][0] * scale, s1 = c[t][1] * scale;
            float s2 = c[t][2] * scale, s3 = c[t][3] * scale;
            if (need_mask) {
                if (k0 > row_a)     s0 = -1e30f;
                if (k0 + 1 > row_a) s1 = -1e30f;
                if (k0 > row_b)     s2 = -1e30f;
                if (k0 + 1 > row_b) s3 = -1e30f;
            }
            c[t][0] = s0; c[t][1] = s1; c[t][2] = s2; c[t][3] = s3;
            mxa = fmaxf(mxa, fmaxf(s0, s1));
            mxb = fmaxf(mxb, fmaxf(s2, s3));
        }
        mxa = fmaxf(mxa, __shfl_xor_sync(0xffffffffu, mxa, 1));
        mxa = fmaxf(mxa, __shfl_xor_sync(0xffffffffu, mxa, 2));
        mxb = fmaxf(mxb, __shfl_xor_sync(0xffffffffu, mxb, 1));
        mxb = fmaxf(mxb, __shfl_xor_sync(0xffffffffu, mxb, 2));

        float mna = fmaxf(ma, mxa), mnb = fmaxf(mb, mxb);
        float cra = __expf(ma - mna), crb = __expf(mb - mnb);
        ma = mna; mb = mnb; la *= cra; lb *= crb;
        #pragma unroll
        for (int t = 0; t < 16; t++) {
            o[t][0] *= cra; o[t][1] *= cra;
            o[t][2] *= crb; o[t][3] *= crb;
        }

        uint4 ahi[4], alo[4];
        #pragma unroll
        for (int k2 = 0; k2 < 4; k2++) {
            int t0 = 2 * k2, t1 = 2 * k2 + 1;
            float p0 = __expf(c[t0][0] - ma), p1 = __expf(c[t0][1] - ma);
            float p2 = __expf(c[t0][2] - mb), p3 = __expf(c[t0][3] - mb);
            float p4 = __expf(c[t1][0] - ma), p5 = __expf(c[t1][1] - ma);
            float p6 = __expf(c[t1][2] - mb), p7 = __expf(c[t1][3] - mb);
            la += p0 + p1 + p4 + p5;
            lb += p2 + p3 + p6 + p7;
            split2h(p0, p1, ahi[k2].x, alo[k2].x);
            split2h(p2, p3, ahi[k2].y, alo[k2].y);
            split2h(p4, p5, ahi[k2].z, alo[k2].z);
            split2h(p6, p7, ahi[k2].w, alo[k2].w);
        }

        #pragma unroll
        for (int k2 = 0; k2 < 4; k2++) {
            #pragma unroll
            for (int t2 = 0; t2 < 16; t2++) {
                uint2 vf = *(const uint2*)&vsm[((t2 * 4 + k2) * 32 + lane) * 2];
                MMA16816(o[t2], ahi[k2], vf.x, vf.y);
                MMA16816(o[t2], alo[k2], vf.x, vf.y);
            }
        }
    }

    la += __shfl_xor_sync(0xffffffffu, la, 1);
    la += __shfl_xor_sync(0xffffffffu, la, 2);
    lb += __shfl_xor_sync(0xffffffffu, lb, 1);
    lb += __shfl_xor_sync(0xffffffffu, lb, 2);
    float ia = 1.f / la, ib = 1.f / lb;

    const int b = bh >> 4, nh = bh & 15;
    const int mt = b * 128 + ((q0 >> 4) + wid);
    #pragma unroll
    for (int t2 = 0; t2 < 16; t2++) {
        int kt2 = nh * 8 + (t2 >> 1);
        size_t base = (((size_t)mt * 128 + kt2) * 32 + lane) * 8 + 2 * (t2 & 1);
        uint32_t h, l;
        split2h(o[t2][0] * ia, o[t2][1] * ia, h, l);
        g_cf[base] = h;     g_cf[base + 4] = l;
        split2h(o[t2][2] * ib, o[t2][3] * ib, h, l);
        g_cf[base + 1] = h; g_cf[base + 5] = l;
    }
}

// ---------------------------------------------------------------------------
// kernel_launch
// ---------------------------------------------------------------------------
extern "C" void kernel_launch(void* const* d_in, const int* in_sizes, int n_in,
                              void* d_out, int out_size)
{
    const float* x    = (const float*)d_in[0];
    const float* wqkv = (const float*)d_in[2];
    const float* wo   = (const float*)d_in[3];

    float* qkv_p;
    uint32_t *xf_p, *cf_p, *wqkvf_p, *wof_p;
    cudaGetSymbolAddress((void**)&qkv_p, g_qkv);
    cudaGetSymbolAddress((void**)&xf_p, g_xf);
    cudaGetSymbolAddress((void**)&cf_p, g_cf);
    cudaGetSymbolAddress((void**)&wqkvf_p, g_wqkvf);
    cudaGetSymbolAddress((void**)&wof_p, g_wof);

    cudaFuncSetAttribute(gemm_frag, cudaFuncAttributeMaxDynamicSharedMemorySize, GEMM_SMEM);
    cudaFuncSetAttribute(attn_mma, cudaFuncAttributeMaxDynamicSharedMemorySize, ATTN_SMEM);

    trig_kernel<<<(S_ * 64 + 255) / 256, 256>>>();
    wfrag_kernel<<<dim3(H_ / 32, NQKV / 32), dim3(32, 8)>>>(wqkv, wqkvf_p, H_, NQKV);
    wfrag_kernel<<<dim3(H_ / 32, H_ / 32), dim3(32, 8)>>>(wo, wof_p, H_, H_);
    afrag_kernel<<<(M_ * H_ / 4) / 256, 256>>>(x, xf_p, M_, H_);

    gemm_frag<<<dim3(NQKV / 128, M_ / 128), 256, GEMM_SMEM>>>(xf_p, wqkvf_p, qkv_p, M_, NQKV, H_);
    prep_kernel<<<dim3(32, 32), 256>>>();
    attn_mma<<<dim3(S_ / 128, B_ * NH_), 256, ATTN_SMEM>>>();
    gemm_frag<<<dim3(H_ / 128, M_ / 128), 256, GEMM_SMEM>>>(cf_p, wof_p, (float*)d_out, M_, H_, H_);
}